// round 7
// baseline (speedup 1.0000x reference)
#include <cuda_runtime.h>
#include <cuda_bf16.h>
#include <cstdint>

// ============================================================================
// 4-layer pyramidal BiGRU. B=32, H=512, 3H=1536.
// Layers l=0..3: T = 1024,512,256,128 ; din = 240,2048,2048,2048
// ============================================================================

#define REC_THREADS 256

// ---------------- static device scratch ----------------
__device__ float g_xzf[50331648];                 // [32][1024][1536] max
__device__ float g_xzb[50331648];
__device__ unsigned int g_flag[2 * 512];          // [dir][64 ctas] stride-8
__device__ unsigned char g_mask[65536];           // per-layer offsets
__device__ __nv_bfloat16 g_whi[19611648], g_wlo[19611648];
__device__ __nv_bfloat16 g_inhi[7864320],  g_inlo[7864320];
__device__ __nv_bfloat16 g_yh0[33554432],  g_yl0[33554432];
__device__ __nv_bfloat16 g_yh1[16777216],  g_yl1[16777216];
__device__ __nv_bfloat16 g_hhi[4 * 16384], g_hlo[4 * 16384];

// ---------------- mma / ldmatrix / cp.async ----------------
#define MMA_BF16(c, a, b0, b1)                                              \
    asm volatile("mma.sync.aligned.m16n8k16.row.col.f32.bf16.bf16.f32 "     \
        "{%0,%1,%2,%3}, {%4,%5,%6,%7}, {%8,%9}, {%0,%1,%2,%3};"             \
        : "+f"((c)[0]), "+f"((c)[1]), "+f"((c)[2]), "+f"((c)[3])            \
        : "r"((a)[0]), "r"((a)[1]), "r"((a)[2]), "r"((a)[3]),               \
          "r"(b0), "r"(b1))

#define LDSM4(R, addr)                                                      \
    asm volatile("ldmatrix.sync.aligned.m8n8.x4.shared.b16 "                \
        "{%0,%1,%2,%3}, [%4];"                                              \
        : "=r"((R)[0]), "=r"((R)[1]), "=r"((R)[2]), "=r"((R)[3])            \
        : "r"(addr))

#define LDSM4T(R, addr)                                                     \
    asm volatile("ldmatrix.sync.aligned.m8n8.x4.trans.shared.b16 "          \
        "{%0,%1,%2,%3}, [%4];"                                              \
        : "=r"((R)[0]), "=r"((R)[1]), "=r"((R)[2]), "=r"((R)[3])            \
        : "r"(addr))

__device__ __forceinline__ unsigned int smaddr(const void* p) {
    return (unsigned int)__cvta_generic_to_shared(p);
}
__device__ __forceinline__ void cpa16(unsigned int dst, const void* src) {
    asm volatile("cp.async.cg.shared.global [%0], [%1], 16;"
                 :: "r"(dst), "l"(src) : "memory");
}
#define CPA_COMMIT() asm volatile("cp.async.commit_group;" ::: "memory")
#define CPA_WAIT0()  asm volatile("cp.async.wait_group 0;" ::: "memory")

__device__ __forceinline__ unsigned int bfpack(float a, float b) {
    __nv_bfloat162 h = __floats2bfloat162_rn(a, b);
    return *reinterpret_cast<unsigned int*>(&h);
}

// ============================================================================
// prep kernel (unchanged)
// ============================================================================
__device__ __forceinline__ void cvt4(float4 v, uint2& hi, uint2& lo) {
    __nv_bfloat162 h0 = __floats2bfloat162_rn(v.x, v.y);
    __nv_bfloat162 h1 = __floats2bfloat162_rn(v.z, v.w);
    float2 f0 = __bfloat1622float2(h0);
    float2 f1 = __bfloat1622float2(h1);
    __nv_bfloat162 l0 = __floats2bfloat162_rn(v.x - f0.x, v.y - f0.y);
    __nv_bfloat162 l1 = __floats2bfloat162_rn(v.z - f1.x, v.w - f1.y);
    hi.x = *(unsigned int*)&h0; hi.y = *(unsigned int*)&h1;
    lo.x = *(unsigned int*)&l0; lo.y = *(unsigned int*)&l1;
}

#define WSZ0 368640
#define WSZ1 3145728

__global__ void prep_kernel(const float* __restrict__ in,
                            const float* w0, const float* w1, const float* w2,
                            const float* w3, const float* w4, const float* w5,
                            const float* w6, const float* w7) {
    const float* ws[8] = {w0, w1, w2, w3, w4, w5, w6, w7};
    const int sz[8]  = {WSZ0, WSZ0, WSZ1, WSZ1, WSZ1, WSZ1, WSZ1, WSZ1};
    const int off[8] = {0, WSZ0, 2 * WSZ0, 2 * WSZ0 + WSZ1, 2 * WSZ0 + 2 * WSZ1,
                        2 * WSZ0 + 3 * WSZ1, 2 * WSZ0 + 4 * WSZ1, 2 * WSZ0 + 5 * WSZ1};
    const int gid = blockIdx.x * blockDim.x + threadIdx.x;
    const int stride = gridDim.x * blockDim.x;

    #pragma unroll 1
    for (int w = 0; w < 8; ++w) {
        const float4* W = (const float4*)ws[w];
        uint2* hi = (uint2*)(g_whi + off[w]);
        uint2* lo = (uint2*)(g_wlo + off[w]);
        int n4 = sz[w] >> 2;
        for (int i = gid; i < n4; i += stride) {
            uint2 h, l; cvt4(__ldg(W + i), h, l);
            hi[i] = h; lo[i] = l;
        }
    }
    {
        const float4* X = (const float4*)in;
        uint2* hi = (uint2*)g_inhi; uint2* lo = (uint2*)g_inlo;
        for (int i = gid; i < (7864320 >> 2); i += stride) {
            uint2 h, l; cvt4(__ldg(X + i), h, l);
            hi[i] = h; lo[i] = l;
        }
    }
    for (int r = gid; r < 32768; r += stride) {
        const float4* p = (const float4*)(in + (size_t)r * 240);
        bool any = false;
        for (int i = 0; i < 60; ++i) {
            float4 v = __ldg(p + i);
            any = any | (v.x != 0.f) | (v.y != 0.f) | (v.z != 0.f) | (v.w != 0.f);
            if (any) break;
        }
        g_mask[r] = any ? 1 : 0;
    }
    for (int i = gid; i < 2 * 512; i += stride) g_flag[i] = 0u;
}

// ============================================================================
// Input-projection GEMM: bf16 hi/lo, mma.sync 128x256x16 tile, fwd+bwd via
// grid.z, masked-tile skip, cp.async DOUBLE-BUFFERED mainloop.
// Stage layout (bf16 elems): a_hi[3072] a_lo[3072] w_hi[4224] w_lo[4224]
// ============================================================================
#define G_ASZ 3072
#define G_WSZ 4224
#define G_STAGE ((2 * G_ASZ + 2 * G_WSZ) * 2)     // 29184 bytes
#define GSMEM (2 * G_STAGE)

__global__ void __launch_bounds__(256, 1) gemm_xz(
    const __nv_bfloat16* __restrict__ Ahi, const __nv_bfloat16* __restrict__ Alo,
    int lda,
    const __nv_bfloat16* __restrict__ WhiF, const __nv_bfloat16* __restrict__ WloF,
    const __nv_bfloat16* __restrict__ WhiB, const __nv_bfloat16* __restrict__ WloB,
    const float* __restrict__ biasF, const float* __restrict__ biasB,
    float* __restrict__ Cf, float* __restrict__ Cb,
    int K, int Tcur, const unsigned char* __restrict__ mask) {
    extern __shared__ __align__(16) char gsm[];

    const int dir = blockIdx.z;
    const int rev = dir;
    const __nv_bfloat16* Whi = dir ? WhiB : WhiF;
    const __nv_bfloat16* Wlo = dir ? WloB : WloF;
    const float* bias = dir ? biasB : biasF;
    float* C = dir ? Cb : Cf;

    const int tid  = threadIdx.x;
    const int lane = tid & 31, wid = tid >> 5;
    const int g = lane >> 2, t4 = lane & 3;
    const int warpM = wid & 3, warpN = wid >> 2;
    const int m0 = blockIdx.y << 7, n0 = blockIdx.x << 8;

    {
        const int b  = m0 / Tcur;
        const int t0 = m0 - b * Tcur;
        const int ttmin = rev ? (Tcur - 128 - t0) : t0;
        if (mask[b * Tcur + ttmin] == 0) return;
    }

    const int ar = tid >> 1;
    const int ak = (tid & 1) << 3;
    const int wk = tid >> 4;
    const int wc = (tid & 15) << 4;

    const __nv_bfloat16 *pAh, *pAl;
    {
        int m  = m0 + ar;
        int bi = m / Tcur;
        int t  = m - bi * Tcur;
        int tt = rev ? (Tcur - 1 - t) : t;
        size_t base = ((size_t)bi * Tcur + tt) * lda + ak;
        pAh = Ahi + base; pAl = Alo + base;
    }
    const __nv_bfloat16* pWh = Whi + (size_t)wk * 1536 + n0 + wc;
    const __nv_bfloat16* pWl = Wlo + (size_t)wk * 1536 + n0 + wc;

    // per-thread fill byte offsets within a stage
    const unsigned int smBase = smaddr(gsm);
    const unsigned int dA_hi = (unsigned)((ar * 24 + ak) * 2);
    const unsigned int dA_lo = dA_hi + G_ASZ * 2;
    const unsigned int dW_hi = (unsigned)((2 * G_ASZ + wk * 264 + wc) * 2);
    const unsigned int dW_lo = dW_hi + G_WSZ * 2;

    // ldmatrix byte offsets within a stage
    const int aRowL = warpM * 32 + (lane & 15);
    const int aKofL = (lane & 16) >> 1;
    const unsigned int oAhi = (unsigned)((aRowL * 24 + aKofL) * 2);
    const unsigned int oAlo = oAhi + G_ASZ * 2;
    const int bCol = warpN * 128 + ((lane & 16) >> 1);
    const unsigned int oBhi = (unsigned)((2 * G_ASZ + (lane & 15) * 264 + bCol) * 2);
    const unsigned int oBlo = oBhi + G_WSZ * 2;

    float c_[2][16][4];
    #pragma unroll
    for (int mt = 0; mt < 2; ++mt)
        #pragma unroll
        for (int nt = 0; nt < 16; ++nt)
            #pragma unroll
            for (int i = 0; i < 4; ++i) c_[mt][nt][i] = 0.f;

    const int NT = K >> 4;

    // prologue: fill stage 0
    {
        const unsigned int sb = smBase;
        cpa16(sb + dA_hi, pAh);
        cpa16(sb + dA_lo, pAl);
        cpa16(sb + dW_hi,      pWh);
        cpa16(sb + dW_hi + 16, pWh + 8);
        cpa16(sb + dW_lo,      pWl);
        cpa16(sb + dW_lo + 16, pWl + 8);
        CPA_COMMIT();
    }

    for (int kt = 0; kt < NT; ++kt) {
        CPA_WAIT0();
        __syncthreads();

        if (kt + 1 < NT) {
            const int k0 = (kt + 1) << 4;
            const unsigned int sb = smBase + ((kt + 1) & 1) * G_STAGE;
            const __nv_bfloat16* qh = pWh + (size_t)k0 * 1536;
            const __nv_bfloat16* ql = pWl + (size_t)k0 * 1536;
            cpa16(sb + dA_hi, pAh + k0);
            cpa16(sb + dA_lo, pAl + k0);
            cpa16(sb + dW_hi,      qh);
            cpa16(sb + dW_hi + 16, qh + 8);
            cpa16(sb + dW_lo,      ql);
            cpa16(sb + dW_lo + 16, ql + 8);
            CPA_COMMIT();
        }

        const unsigned int sb = smBase + (kt & 1) * G_STAGE;
        unsigned int afh[2][4], afl[2][4];
        #pragma unroll
        for (int mt = 0; mt < 2; ++mt) {
            LDSM4(afh[mt], sb + oAhi + mt * 768);
            LDSM4(afl[mt], sb + oAlo + mt * 768);
        }

        #pragma unroll
        for (int p = 0; p < 8; ++p) {
            unsigned int bh[4], bl[4];
            LDSM4T(bh, sb + oBhi + p * 32);
            LDSM4T(bl, sb + oBlo + p * 32);
            #pragma unroll
            for (int s = 0; s < 2; ++s) {
                const int nt = 2 * p + s;
                #pragma unroll
                for (int mt = 0; mt < 2; ++mt) {
                    MMA_BF16(c_[mt][nt], afh[mt], bh[2 * s], bh[2 * s + 1]);
                    MMA_BF16(c_[mt][nt], afh[mt], bl[2 * s], bl[2 * s + 1]);
                    MMA_BF16(c_[mt][nt], afl[mt], bh[2 * s], bh[2 * s + 1]);
                }
            }
        }
    }

    #pragma unroll
    for (int nt = 0; nt < 16; ++nt) {
        int col = n0 + warpN * 128 + nt * 8 + t4 * 2;
        float bx = __ldg(bias + col);
        float by = __ldg(bias + col + 1);
        #pragma unroll
        for (int mt = 0; mt < 2; ++mt) {
            int r = m0 + warpM * 32 + mt * 16 + g;
            float2 o0 = {c_[mt][nt][0] + bx, c_[mt][nt][1] + by};
            float2 o1 = {c_[mt][nt][2] + bx, c_[mt][nt][3] + by};
            *(float2*)(C + (size_t)r * 1536 + col)       = o0;
            *(float2*)(C + (size_t)(r + 8) * 1536 + col) = o1;
        }
    }
}

// ============================================================================
// Recurrence on tensor cores, k-split across 8 warps.
//   Warp w owns kt in [4w, 4w+4): computes ALL 3 gates x 2 mt partials.
//   B frags for own chunk in regs (48), A via ldmatrix (128 LDSM/step total).
//   Partials reduced (8 terms) in SMEM by the scalar epilogue.
// SMEM: ahi[32][520] | alo[32][520] (bf16) | part[8][3][32][8] f32 | hp[256]
// ============================================================================
#define LDK 520
#define REC_SMEM (2 * 32 * LDK * 2 + 8 * 3 * 256 * 4 + 256 * 4)

__global__ void __launch_bounds__(REC_THREADS, 1) gru_rec_kernel(
    const float* __restrict__ xzf, const float* __restrict__ xzb,
    const float* __restrict__ rkf, const float* __restrict__ rkb,
    const float* __restrict__ bf,  const float* __restrict__ bb,
    const unsigned char* __restrict__ mask,
    float* __restrict__ y32,
    __nv_bfloat16* __restrict__ yhi, __nv_bfloat16* __restrict__ ylo,
    unsigned char* __restrict__ nextmask,
    int T, int flagBase, int writeHidden, float* __restrict__ hiddenOut) {
    extern __shared__ __align__(16) char smraw[];
    __nv_bfloat16* sh_ahi = (__nv_bfloat16*)smraw;
    __nv_bfloat16* sh_alo = sh_ahi + 32 * LDK;
    float* sh_part = (float*)(sh_alo + 32 * LDK);   // [8][3][32][8]
    float* sh_hp   = sh_part + 8 * 3 * 256;

    const int tid  = threadIdx.x;
    const int lane = tid & 31, wid = tid >> 5;
    const int dir = blockIdx.x >> 6;
    const int j   = blockIdx.x & 63;
    const int cb  = j << 3;
    const int b   = tid >> 3;
    const int c8  = tid & 7;
    const int col = cb + c8;

    const float* xz = dir ? xzb : xzf;
    const float* rk = dir ? rkb : rkf;
    const float* bi = (dir ? bb : bf) + 1536;

    sh_hp[tid] = 0.f;

    // ---- B-fragment preload: warp w owns kt = 4w..4w+3, all 3 gates ----
    const int t4 = lane & 3;
    const int gcol = lane >> 2;
    unsigned int Bh0[3][4], Bh1[3][4], Bl0[3][4], Bl1[3][4];
    #pragma unroll 1
    for (int gate = 0; gate < 3; ++gate) {
        const float* wcolp = rk + gate * 512 + cb + gcol;
        #pragma unroll
        for (int q = 0; q < 4; ++q) {
            int k0 = (wid * 4 + q) * 16 + t4 * 2;
            float w00 = __ldg(wcolp + (size_t)(k0)     * 1536);
            float w01 = __ldg(wcolp + (size_t)(k0 + 1) * 1536);
            float w10 = __ldg(wcolp + (size_t)(k0 + 8) * 1536);
            float w11 = __ldg(wcolp + (size_t)(k0 + 9) * 1536);
            __nv_bfloat16 h00 = __float2bfloat16(w00), h01 = __float2bfloat16(w01);
            __nv_bfloat16 h10 = __float2bfloat16(w10), h11 = __float2bfloat16(w11);
            Bh0[gate][q] = ((unsigned)*(unsigned short*)&h01 << 16) | *(unsigned short*)&h00;
            Bh1[gate][q] = ((unsigned)*(unsigned short*)&h11 << 16) | *(unsigned short*)&h10;
            Bl0[gate][q] = bfpack(w00 - __bfloat162float(h00), w01 - __bfloat162float(h01));
            Bl1[gate][q] = bfpack(w10 - __bfloat162float(h10), w11 - __bfloat162float(h11));
        }
    }
    const float bz = __ldg(bi + col);
    const float br = __ldg(bi + 512 + col);
    const float bh = __ldg(bi + 1024 + col);
    __syncthreads();

    // ldmatrix bases (A = h matrix): row = mt*16 + (lane&15), khalf = lane>>4
    const unsigned int aB0 = smaddr(sh_ahi) +
        (unsigned)((((lane & 15)) * LDK + ((lane >> 4) << 3)) * 2) + (unsigned)(wid * 128);
    const unsigned int aB1 = aB0 + (unsigned)(16 * LDK * 2);
    const unsigned int loOfs = (unsigned)(32 * LDK * 2);

    unsigned int* myflag = g_flag + dir * 512 + j * 8;
    const unsigned int* pollflag = g_flag + dir * 512 + (tid & 63) * 8;
    const bool maskWriter = (nextmask != nullptr) && (dir == 0) && (j == 0) && (c8 == 0);
    unsigned char mprev = 0;

    for (int t = 0; t < T; ++t) {
        const int tsrc = dir ? (T - 1 - t) : t;
        const size_t xoff = ((size_t)b * T + t) * 1536;
        const float x0 = __ldg(xz + xoff + col);
        const float x1 = __ldg(xz + xoff + 512 + col);
        const float x2 = __ldg(xz + xoff + 1024 + col);
        const unsigned char m = mask[b * T + tsrc];

        if (t > 0) {
            if (tid < 64) {
                unsigned int v;
                unsigned int target = (unsigned int)(flagBase + t);
                do {
                    asm volatile("ld.acquire.gpu.global.u32 %0, [%1];"
                                 : "=r"(v) : "l"(pollflag) : "memory");
                } while (v < target);
            }
            __syncthreads();

            // ---- stage h (bf16 hi/lo) via cp.async ----
            const size_t hsrc = (size_t)(((t & 1) * 2 + dir)) << 14;
            const __nv_bfloat16* ghi = g_hhi + hsrc;
            const __nv_bfloat16* glo = g_hlo + hsrc;
            #pragma unroll
            for (int q = 0; q < 8; ++q) {
                int v = q * 256 + tid;
                int bb2 = v >> 6, kc = v & 63;
                cpa16(smaddr(sh_ahi + bb2 * LDK + kc * 8), ghi + (bb2 << 9) + kc * 8);
                cpa16(smaddr(sh_alo + bb2 * LDK + kc * 8), glo + (bb2 << 9) + kc * 8);
            }
            CPA_COMMIT();
            CPA_WAIT0();
            __syncthreads();

            // ---- each warp: 4 kt x (4 ldsm + 18 mma) ----
            float acc[3][2][4];
            #pragma unroll
            for (int gg = 0; gg < 3; ++gg)
                #pragma unroll
                for (int mt = 0; mt < 2; ++mt)
                    #pragma unroll
                    for (int i = 0; i < 4; ++i) acc[gg][mt][i] = 0.f;

            #pragma unroll
            for (int q = 0; q < 4; ++q) {
                unsigned int ah[2][4], al[2][4];
                LDSM4(ah[0], aB0 + q * 32);
                LDSM4(ah[1], aB1 + q * 32);
                LDSM4(al[0], aB0 + loOfs + q * 32);
                LDSM4(al[1], aB1 + loOfs + q * 32);
                #pragma unroll
                for (int gg = 0; gg < 3; ++gg) {
                    #pragma unroll
                    for (int mt = 0; mt < 2; ++mt) {
                        MMA_BF16(acc[gg][mt], ah[mt], Bh0[gg][q], Bh1[gg][q]);
                        MMA_BF16(acc[gg][mt], ah[mt], Bl0[gg][q], Bl1[gg][q]);
                        MMA_BF16(acc[gg][mt], al[mt], Bh0[gg][q], Bh1[gg][q]);
                    }
                }
            }
            // partial store
            const int row = lane >> 2, cq = (lane & 3) << 1;
            #pragma unroll
            for (int gg = 0; gg < 3; ++gg) {
                #pragma unroll
                for (int mt = 0; mt < 2; ++mt) {
                    float* gp = sh_part + (wid * 3 + gg) * 256 + (mt * 16 + row) * 8 + cq;
                    gp[0]  = acc[gg][mt][0];
                    gp[1]  = acc[gg][mt][1];
                    gp[64] = acc[gg][mt][2];
                    gp[65] = acc[gg][mt][3];
                }
            }
            __syncthreads();
        }

        // ---- scalar epilogue ----
        float iz = bz, ir = br, ic = bh;
        if (t > 0) {
            #pragma unroll
            for (int w = 0; w < 8; ++w) {
                iz += sh_part[(w * 3 + 0) * 256 + tid];
                ir += sh_part[(w * 3 + 1) * 256 + tid];
                ic += sh_part[(w * 3 + 2) * 256 + tid];
            }
        }

        const float zg = 1.f / (1.f + expf(-(x0 + iz)));
        const float rg = 1.f / (1.f + expf(-(x1 + ir)));
        const float hh = tanhf(x2 + rg * ic);
        const float hp = sh_hp[tid];
        const float hn = zg * hp + (1.f - zg) * hh;
        const float hsel = m ? hn : hp;
        const float yval = m ? hn : 0.f;
        sh_hp[tid] = hsel;

        // ---- critical path: publish h + flag ----
        const size_t hdst = (size_t)((((t + 1) & 1) * 2 + dir)) << 14;
        __nv_bfloat16 h16 = __float2bfloat16(hsel);
        __nv_bfloat16 l16 = __float2bfloat16(hsel - __bfloat162float(h16));
        g_hhi[hdst + (b << 9) + col] = h16;
        g_hlo[hdst + (b << 9) + col] = l16;
        __syncthreads();
        if (tid == 0) {
            unsigned int v = (unsigned int)(flagBase + t + 1);
            asm volatile("st.release.gpu.global.u32 [%0], %1;"
                         :: "l"(myflag), "r"(v) : "memory");
        }

        // ---- off critical path: outputs ----
        const size_t yidx = ((size_t)b * T + tsrc) * 1024 + (dir << 9) + col;
        if (yhi) {
            __nv_bfloat16 yh16 = __float2bfloat16(yval);
            yhi[yidx] = yh16;
            ylo[yidx] = __float2bfloat16(yval - __bfloat162float(yh16));
        }
        if (y32) y32[yidx] = yval;
        if (writeHidden && t == T - 1)
            hiddenOut[(b << 10) + (dir << 9) + col] = hsel;
        if (maskWriter) {
            if ((t & 1) == 0) mprev = m;
            else nextmask[b * (T >> 1) + (t >> 1)] = (unsigned char)(mprev | m);
        }
    }
}

// ============================================================================
// Launch sequence (graph-capturable)
// ============================================================================
extern "C" void kernel_launch(void* const* d_in, const int* in_sizes, int n_in,
                              void* d_out, int out_size) {
    (void)in_sizes; (void)n_in; (void)out_size;
    const float* inputs = (const float*)d_in[0];

    const float *k_[4][2], *r_[4][2], *bi_[4][2];
    for (int l = 0; l < 4; ++l)
        for (int d = 0; d < 2; ++d) {
            int base = 3 + l * 6 + d * 3;
            k_[l][d]  = (const float*)d_in[base + 0];
            r_[l][d]  = (const float*)d_in[base + 1];
            bi_[l][d] = (const float*)d_in[base + 2];
        }

    float *xzf, *xzb;
    unsigned char* mk;
    __nv_bfloat16 *whi, *wlo, *inhi, *inlo, *yh0, *yl0, *yh1, *yl1;
    cudaGetSymbolAddress((void**)&xzf, g_xzf);
    cudaGetSymbolAddress((void**)&xzb, g_xzb);
    cudaGetSymbolAddress((void**)&mk, g_mask);
    cudaGetSymbolAddress((void**)&whi, g_whi);
    cudaGetSymbolAddress((void**)&wlo, g_wlo);
    cudaGetSymbolAddress((void**)&inhi, g_inhi);
    cudaGetSymbolAddress((void**)&inlo, g_inlo);
    cudaGetSymbolAddress((void**)&yh0, g_yh0);
    cudaGetSymbolAddress((void**)&yl0, g_yl0);
    cudaGetSymbolAddress((void**)&yh1, g_yh1);
    cudaGetSymbolAddress((void**)&yl1, g_yl1);

    cudaFuncSetAttribute(gru_rec_kernel,
                         cudaFuncAttributeMaxDynamicSharedMemorySize, REC_SMEM);
    cudaFuncSetAttribute(gemm_xz,
                         cudaFuncAttributeMaxDynamicSharedMemorySize, GSMEM);

    float* outp = (float*)d_out;
    float* hid  = outp + (size_t)32 * 128 * 1024;

    prep_kernel<<<2048, 256>>>(inputs, k_[0][0], k_[0][1], k_[1][0], k_[1][1],
                               k_[2][0], k_[2][1], k_[3][0], k_[3][1]);

    const int Ts[4]   = {1024, 512, 256, 128};
    const int Ks[4]   = {240, 2048, 2048, 2048};
    const int ldas[4] = {240, 2048, 2048, 2048};
    const int woff[4][2] = {{0, WSZ0},
                            {2 * WSZ0, 2 * WSZ0 + WSZ1},
                            {2 * WSZ0 + 2 * WSZ1, 2 * WSZ0 + 3 * WSZ1},
                            {2 * WSZ0 + 4 * WSZ1, 2 * WSZ0 + 5 * WSZ1}};
    const int moff[4]  = {0, 32768, 49152, 57344};
    const int fbase[4] = {0, 1024, 1536, 1792};

    const __nv_bfloat16* Ah[4] = {inhi, yh0, yh1, yh0};
    const __nv_bfloat16* Al[4] = {inlo, yl0, yl1, yl0};
    __nv_bfloat16* Yh[4] = {yh0, yh1, yh0, nullptr};
    __nv_bfloat16* Yl[4] = {yl0, yl1, yl0, nullptr};
    float* Y32[4] = {nullptr, nullptr, nullptr, outp};

    for (int l = 0; l < 4; ++l) {
        const int T = Ts[l], K = Ks[l];
        const int rows = 32 * T;

        dim3 grid(6, rows / 128, 2);
        gemm_xz<<<grid, 256, GSMEM>>>(Ah[l], Al[l], ldas[l],
                               whi + woff[l][0], wlo + woff[l][0],
                               whi + woff[l][1], wlo + woff[l][1],
                               bi_[l][0], bi_[l][1],
                               xzf, xzb, K, T, mk + moff[l]);

        gru_rec_kernel<<<128, REC_THREADS, REC_SMEM>>>(
            xzf, xzb, r_[l][0], r_[l][1], bi_[l][0], bi_[l][1],
            mk + moff[l], Y32[l], Yh[l], Yl[l],
            (l < 3) ? (mk + moff[l + 1]) : nullptr,
            T, fbase[l], (l == 3) ? 1 : 0, hid);
    }
}

// round 8
// speedup vs baseline: 1.1256x; 1.1256x over previous
#include <cuda_runtime.h>
#include <cuda_bf16.h>
#include <cstdint>

// ============================================================================
// 4-layer pyramidal BiGRU. B=32, H=512, 3H=1536.
// Layers l=0..3: T = 1024,512,256,128 ; din = 240,2048,2048,2048
// ============================================================================

#define REC_THREADS 256

// ---------------- static device scratch ----------------
__device__ float g_xzf[50331648];                 // [32][1024][1536] max
__device__ float g_xzb[50331648];
__device__ unsigned int g_flag[2 * 512];          // [dir][64 ctas] stride-8
__device__ unsigned char g_mask[65536];           // per-layer offsets
__device__ __nv_bfloat16 g_whi[19611648], g_wlo[19611648];
__device__ __nv_bfloat16 g_inhi[7864320],  g_inlo[7864320];
__device__ __nv_bfloat16 g_yh0[33554432],  g_yl0[33554432];
__device__ __nv_bfloat16 g_yh1[16777216],  g_yl1[16777216];
__device__ __nv_bfloat16 g_hhi[4 * 16384], g_hlo[4 * 16384];

// ---------------- mma / ldmatrix ----------------
#define MMA_BF16(c, a, b0, b1)                                              \
    asm volatile("mma.sync.aligned.m16n8k16.row.col.f32.bf16.bf16.f32 "     \
        "{%0,%1,%2,%3}, {%4,%5,%6,%7}, {%8,%9}, {%0,%1,%2,%3};"             \
        : "+f"((c)[0]), "+f"((c)[1]), "+f"((c)[2]), "+f"((c)[3])            \
        : "r"((a)[0]), "r"((a)[1]), "r"((a)[2]), "r"((a)[3]),               \
          "r"(b0), "r"(b1))

#define LDSM4(R, addr)                                                      \
    asm volatile("ldmatrix.sync.aligned.m8n8.x4.shared.b16 "                \
        "{%0,%1,%2,%3}, [%4];"                                              \
        : "=r"((R)[0]), "=r"((R)[1]), "=r"((R)[2]), "=r"((R)[3])            \
        : "r"(addr))

#define LDSM4T(R, addr)                                                     \
    asm volatile("ldmatrix.sync.aligned.m8n8.x4.trans.shared.b16 "          \
        "{%0,%1,%2,%3}, [%4];"                                              \
        : "=r"((R)[0]), "=r"((R)[1]), "=r"((R)[2]), "=r"((R)[3])            \
        : "r"(addr))

__device__ __forceinline__ unsigned int smaddr(const void* p) {
    return (unsigned int)__cvta_generic_to_shared(p);
}
__device__ __forceinline__ unsigned int bfpack(float a, float b) {
    __nv_bfloat162 h = __floats2bfloat162_rn(a, b);
    return *reinterpret_cast<unsigned int*>(&h);
}

// ============================================================================
// prep kernel: convert 8 weight matrices + layer-0 input to bf16 hi/lo,
// compute layer-0 mask, zero flags.
// ============================================================================
__device__ __forceinline__ void cvt4(float4 v, uint2& hi, uint2& lo) {
    __nv_bfloat162 h0 = __floats2bfloat162_rn(v.x, v.y);
    __nv_bfloat162 h1 = __floats2bfloat162_rn(v.z, v.w);
    float2 f0 = __bfloat1622float2(h0);
    float2 f1 = __bfloat1622float2(h1);
    __nv_bfloat162 l0 = __floats2bfloat162_rn(v.x - f0.x, v.y - f0.y);
    __nv_bfloat162 l1 = __floats2bfloat162_rn(v.z - f1.x, v.w - f1.y);
    hi.x = *(unsigned int*)&h0; hi.y = *(unsigned int*)&h1;
    lo.x = *(unsigned int*)&l0; lo.y = *(unsigned int*)&l1;
}

#define WSZ0 368640
#define WSZ1 3145728

__global__ void prep_kernel(const float* __restrict__ in,
                            const float* w0, const float* w1, const float* w2,
                            const float* w3, const float* w4, const float* w5,
                            const float* w6, const float* w7) {
    const float* ws[8] = {w0, w1, w2, w3, w4, w5, w6, w7};
    const int sz[8]  = {WSZ0, WSZ0, WSZ1, WSZ1, WSZ1, WSZ1, WSZ1, WSZ1};
    const int off[8] = {0, WSZ0, 2 * WSZ0, 2 * WSZ0 + WSZ1, 2 * WSZ0 + 2 * WSZ1,
                        2 * WSZ0 + 3 * WSZ1, 2 * WSZ0 + 4 * WSZ1, 2 * WSZ0 + 5 * WSZ1};
    const int gid = blockIdx.x * blockDim.x + threadIdx.x;
    const int stride = gridDim.x * blockDim.x;

    #pragma unroll 1
    for (int w = 0; w < 8; ++w) {
        const float4* W = (const float4*)ws[w];
        uint2* hi = (uint2*)(g_whi + off[w]);
        uint2* lo = (uint2*)(g_wlo + off[w]);
        int n4 = sz[w] >> 2;
        for (int i = gid; i < n4; i += stride) {
            uint2 h, l; cvt4(__ldg(W + i), h, l);
            hi[i] = h; lo[i] = l;
        }
    }
    {
        const float4* X = (const float4*)in;
        uint2* hi = (uint2*)g_inhi; uint2* lo = (uint2*)g_inlo;
        for (int i = gid; i < (7864320 >> 2); i += stride) {
            uint2 h, l; cvt4(__ldg(X + i), h, l);
            hi[i] = h; lo[i] = l;
        }
    }
    for (int r = gid; r < 32768; r += stride) {
        const float4* p = (const float4*)(in + (size_t)r * 240);
        bool any = false;
        for (int i = 0; i < 60; ++i) {
            float4 v = __ldg(p + i);
            any = any | (v.x != 0.f) | (v.y != 0.f) | (v.z != 0.f) | (v.w != 0.f);
            if (any) break;
        }
        g_mask[r] = any ? 1 : 0;
    }
    for (int i = gid; i < 2 * 512; i += stride) g_flag[i] = 0u;
}

// ============================================================================
// Input-projection GEMM (round-5 proven version): bf16 hi/lo, mma.sync,
// tile 128x256x16, merged fwd/bwd via grid.z, masked-tile skip.
// ============================================================================
__global__ void __launch_bounds__(256, 1) gemm_xz(
    const __nv_bfloat16* __restrict__ Ahi, const __nv_bfloat16* __restrict__ Alo,
    int lda,
    const __nv_bfloat16* __restrict__ WhiF, const __nv_bfloat16* __restrict__ WloF,
    const __nv_bfloat16* __restrict__ WhiB, const __nv_bfloat16* __restrict__ WloB,
    const float* __restrict__ biasF, const float* __restrict__ biasB,
    float* __restrict__ Cf, float* __restrict__ Cb,
    int K, int Tcur, const unsigned char* __restrict__ mask) {
    __shared__ __align__(16) __nv_bfloat16 a_hi[128 * 24], a_lo[128 * 24];
    __shared__ __align__(16) __nv_bfloat16 w_hi[16 * 264], w_lo[16 * 264];

    const int dir = blockIdx.z;
    const int rev = dir;
    const __nv_bfloat16* Whi = dir ? WhiB : WhiF;
    const __nv_bfloat16* Wlo = dir ? WloB : WloF;
    const float* bias = dir ? biasB : biasF;
    float* C = dir ? Cb : Cf;

    const int tid  = threadIdx.x;
    const int lane = tid & 31, wid = tid >> 5;
    const int g = lane >> 2, t4 = lane & 3;
    const int warpM = wid & 3, warpN = wid >> 2;
    const int m0 = blockIdx.y << 7, n0 = blockIdx.x << 8;

    {
        const int b  = m0 / Tcur;
        const int t0 = m0 - b * Tcur;
        const int ttmin = rev ? (Tcur - 128 - t0) : t0;
        if (mask[b * Tcur + ttmin] == 0) return;
    }

    const int ar = tid >> 1;
    const int ak = (tid & 1) << 3;
    const int wk = tid >> 4;
    const int wc = (tid & 15) << 4;

    const __nv_bfloat16 *pAh, *pAl;
    {
        int m  = m0 + ar;
        int bi = m / Tcur;
        int t  = m - bi * Tcur;
        int tt = rev ? (Tcur - 1 - t) : t;
        size_t base = ((size_t)bi * Tcur + tt) * lda + ak;
        pAh = Ahi + base; pAl = Alo + base;
    }
    const __nv_bfloat16* pWh = Whi + (size_t)wk * 1536 + n0 + wc;
    const __nv_bfloat16* pWl = Wlo + (size_t)wk * 1536 + n0 + wc;

    const int aRowL = warpM * 32 + (lane & 15);
    const int aKofL = (lane & 16) >> 1;
    const unsigned int aHiAddr = smaddr(a_hi) + (unsigned)((aRowL * 24 + aKofL) * 2);
    const unsigned int aLoAddr = smaddr(a_lo) + (unsigned)((aRowL * 24 + aKofL) * 2);
    const int bCol = warpN * 128 + ((lane & 16) >> 1);
    const unsigned int bHiAddr = smaddr(w_hi) + (unsigned)(((lane & 15) * 264 + bCol) * 2);
    const unsigned int bLoAddr = smaddr(w_lo) + (unsigned)(((lane & 15) * 264 + bCol) * 2);

    float c_[2][16][4];
    #pragma unroll
    for (int mt = 0; mt < 2; ++mt)
        #pragma unroll
        for (int nt = 0; nt < 16; ++nt)
            #pragma unroll
            for (int i = 0; i < 4; ++i) c_[mt][nt][i] = 0.f;

    const int NT = K >> 4;
    uint4 rAh = *(const uint4*)pAh;
    uint4 rAl = *(const uint4*)pAl;
    uint4 rWh0 = *(const uint4*)pWh;
    uint4 rWh1 = *(const uint4*)(pWh + 8);
    uint4 rWl0 = *(const uint4*)pWl;
    uint4 rWl1 = *(const uint4*)(pWl + 8);

    for (int kt = 0; kt < NT; ++kt) {
        *(uint4*)(a_hi + ar * 24 + ak) = rAh;
        *(uint4*)(a_lo + ar * 24 + ak) = rAl;
        *(uint4*)(w_hi + wk * 264 + wc)     = rWh0;
        *(uint4*)(w_hi + wk * 264 + wc + 8) = rWh1;
        *(uint4*)(w_lo + wk * 264 + wc)     = rWl0;
        *(uint4*)(w_lo + wk * 264 + wc + 8) = rWl1;
        __syncthreads();

        if (kt + 1 < NT) {
            int k0 = (kt + 1) << 4;
            rAh = *(const uint4*)(pAh + k0);
            rAl = *(const uint4*)(pAl + k0);
            const __nv_bfloat16* qh = pWh + (size_t)k0 * 1536;
            const __nv_bfloat16* ql = pWl + (size_t)k0 * 1536;
            rWh0 = *(const uint4*)qh; rWh1 = *(const uint4*)(qh + 8);
            rWl0 = *(const uint4*)ql; rWl1 = *(const uint4*)(ql + 8);
        }

        unsigned int afh[2][4], afl[2][4];
        #pragma unroll
        for (int mt = 0; mt < 2; ++mt) {
            LDSM4(afh[mt], aHiAddr + mt * 768);
            LDSM4(afl[mt], aLoAddr + mt * 768);
        }

        #pragma unroll
        for (int p = 0; p < 8; ++p) {
            unsigned int bh[4], bl[4];
            LDSM4T(bh, bHiAddr + p * 32);
            LDSM4T(bl, bLoAddr + p * 32);
            #pragma unroll
            for (int s = 0; s < 2; ++s) {
                const int nt = 2 * p + s;
                #pragma unroll
                for (int mt = 0; mt < 2; ++mt) {
                    MMA_BF16(c_[mt][nt], afh[mt], bh[2 * s], bh[2 * s + 1]);
                    MMA_BF16(c_[mt][nt], afh[mt], bl[2 * s], bl[2 * s + 1]);
                    MMA_BF16(c_[mt][nt], afl[mt], bh[2 * s], bh[2 * s + 1]);
                }
            }
        }
        __syncthreads();
    }

    #pragma unroll
    for (int nt = 0; nt < 16; ++nt) {
        int col = n0 + warpN * 128 + nt * 8 + t4 * 2;
        float bx = __ldg(bias + col);
        float by = __ldg(bias + col + 1);
        #pragma unroll
        for (int mt = 0; mt < 2; ++mt) {
            int r = m0 + warpM * 32 + mt * 16 + g;
            float2 o0 = {c_[mt][nt][0] + bx, c_[mt][nt][1] + by};
            float2 o1 = {c_[mt][nt][2] + bx, c_[mt][nt][3] + by};
            *(float2*)(C + (size_t)r * 1536 + col)       = o0;
            *(float2*)(C + (size_t)(r + 8) * 1536 + col) = o1;
        }
    }
}

// ============================================================================
// Recurrence on tensor cores (round-6 structure + chunked staging overlap).
//   Warps 0..5 = (gate, mt): B frags for all K=512 in regs; ldmatrix A.
//   Staging: chunk0 (k<256) by all 256 threads; chunk1 (k>=256) by warps
//   6-7 CONCURRENTLY with warps 0-5 running mma on chunk0.
// SMEM: ahi[32][520] bf16 | alo[32][520] bf16 | gate[3][32][8] f32 | hp[32][8]
// ============================================================================
#define LDK 520
#define REC_SMEM (2 * 32 * LDK * 2 + 3 * 32 * 8 * 4 + 32 * 8 * 4)

__global__ void __launch_bounds__(REC_THREADS, 1) gru_rec_kernel(
    const float* __restrict__ xzf, const float* __restrict__ xzb,
    const float* __restrict__ rkf, const float* __restrict__ rkb,
    const float* __restrict__ bf,  const float* __restrict__ bb,
    const unsigned char* __restrict__ mask,
    float* __restrict__ y32,
    __nv_bfloat16* __restrict__ yhi, __nv_bfloat16* __restrict__ ylo,
    unsigned char* __restrict__ nextmask,
    int T, int flagBase, int writeHidden, float* __restrict__ hiddenOut) {
    extern __shared__ __align__(16) char smraw[];
    __nv_bfloat16* sh_ahi = (__nv_bfloat16*)smraw;                // [32][520]
    __nv_bfloat16* sh_alo = sh_ahi + 32 * LDK;                    // [32][520]
    float* sh_gate = (float*)(sh_alo + 32 * LDK);                 // [3][32][8]
    float* sh_hp   = sh_gate + 3 * 32 * 8;                        // [32][8]

    const int tid  = threadIdx.x;
    const int lane = tid & 31, wid = tid >> 5;
    const int dir = blockIdx.x >> 6;
    const int j   = blockIdx.x & 63;
    const int cb  = j << 3;
    const int b   = tid >> 3;
    const int c8  = tid & 7;
    const int col = cb + c8;

    const float* xz = dir ? xzb : xzf;
    const float* rk = dir ? rkb : rkf;
    const float* bi = (dir ? bb : bf) + 1536;   // b[1]

    for (int i = tid; i < 3 * 256 + 256; i += REC_THREADS) sh_gate[i] = 0.f;

    // ---- B-fragment preload (warps 0..5) ----
    const int gate = wid >> 1;      // 0..2
    const int mt   = wid & 1;       // 0..1
    const int t4   = lane & 3;
    const int gcol = lane >> 2;     // 0..7
    unsigned int Bh0[32], Bh1[32], Bl0[32], Bl1[32];
    if (wid < 6) {
        const float* wcolp = rk + gate * 512 + cb + gcol;
        #pragma unroll 1
        for (int kt = 0; kt < 32; ++kt) {
            int k0 = kt * 16 + t4 * 2;
            float w00 = __ldg(wcolp + (size_t)(k0)     * 1536);
            float w01 = __ldg(wcolp + (size_t)(k0 + 1) * 1536);
            float w10 = __ldg(wcolp + (size_t)(k0 + 8) * 1536);
            float w11 = __ldg(wcolp + (size_t)(k0 + 9) * 1536);
            __nv_bfloat16 h00 = __float2bfloat16(w00), h01 = __float2bfloat16(w01);
            __nv_bfloat16 h10 = __float2bfloat16(w10), h11 = __float2bfloat16(w11);
            Bh0[kt] = ((unsigned)*(unsigned short*)&h01 << 16) | *(unsigned short*)&h00;
            Bh1[kt] = ((unsigned)*(unsigned short*)&h11 << 16) | *(unsigned short*)&h10;
            Bl0[kt] = bfpack(w00 - __bfloat162float(h00), w01 - __bfloat162float(h01));
            Bl1[kt] = bfpack(w10 - __bfloat162float(h10), w11 - __bfloat162float(h11));
        }
    }
    const float bz = __ldg(bi + col);
    const float br = __ldg(bi + 512 + col);
    const float bh = __ldg(bi + 1024 + col);
    __syncthreads();

    // ldmatrix lane address (A = h matrix, rows = batch)
    const unsigned int aBase = smaddr(sh_ahi) +
        (unsigned)(((mt * 16 + (lane & 15)) * LDK + ((lane >> 4) << 3)) * 2);
    const unsigned int aLoBase = aBase + 32 * LDK * 2;

    unsigned int* myflag = g_flag + dir * 512 + j * 8;
    const unsigned int* pollflag = g_flag + dir * 512 + (tid & 63) * 8;
    const bool maskWriter = (nextmask != nullptr) && (dir == 0) && (j == 0) && (c8 == 0);
    unsigned char mprev = 0;

    for (int t = 0; t < T; ++t) {
        const int tsrc = dir ? (T - 1 - t) : t;
        const size_t xoff = ((size_t)b * T + t) * 1536;
        const float x0 = __ldg(xz + xoff + col);
        const float x1 = __ldg(xz + xoff + 512 + col);
        const float x2 = __ldg(xz + xoff + 1024 + col);
        const unsigned char m = mask[b * T + tsrc];

        if (t > 0) {
            // ---- wait for step t-1 of all CTAs in this direction ----
            if (tid < 64) {
                unsigned int v;
                unsigned int target = (unsigned int)(flagBase + t);
                do {
                    asm volatile("ld.acquire.gpu.global.u32 %0, [%1];"
                                 : "=r"(v) : "l"(pollflag) : "memory");
                } while (v < target);
            }
            __syncthreads();

            const size_t hsrc = (size_t)(((t & 1) * 2 + dir)) << 14;
            const __nv_bfloat16* ghi = g_hhi + hsrc;
            const __nv_bfloat16* glo = g_hlo + hsrc;

            // ---- stage chunk0 (k 0..255), all 256 threads ----
            {
                uint4 hv[4], lv[4];
                #pragma unroll
                for (int q = 0; q < 4; ++q) {
                    int v = q * 256 + tid;          // 0..1023
                    int bb2 = v >> 5, kc = v & 31;  // row, 8-elem chunk
                    hv[q] = __ldcg((const uint4*)(ghi + (bb2 << 9) + kc * 8));
                    lv[q] = __ldcg((const uint4*)(glo + (bb2 << 9) + kc * 8));
                }
                #pragma unroll
                for (int q = 0; q < 4; ++q) {
                    int v = q * 256 + tid;
                    int bb2 = v >> 5, kc = v & 31;
                    *(uint4*)(sh_ahi + bb2 * LDK + kc * 8) = hv[q];
                    *(uint4*)(sh_alo + bb2 * LDK + kc * 8) = lv[q];
                }
            }
            __syncthreads();   // chunk0 ready

            // ---- overlap: warps 0-5 mma chunk0; warps 6-7 stage chunk1 ----
            float acc[4][4];
            #pragma unroll
            for (int i = 0; i < 4; ++i)
                #pragma unroll
                for (int q = 0; q < 4; ++q) acc[i][q] = 0.f;

            if (wid < 6) {
                #pragma unroll
                for (int kt = 0; kt < 16; ++kt) {
                    unsigned int ah[4], al[4];
                    LDSM4(ah, aBase + kt * 32);
                    LDSM4(al, aLoBase + kt * 32);
                    float* c = acc[kt & 3];
                    MMA_BF16(c, ah, Bh0[kt], Bh1[kt]);
                    MMA_BF16(c, ah, Bl0[kt], Bl1[kt]);
                    MMA_BF16(c, al, Bh0[kt], Bh1[kt]);
                }
            } else {
                // stage chunk1 (k 256..511): 64 threads x 32 uint4
                const int lt = tid - 192;
                #pragma unroll
                for (int qq = 0; qq < 4; ++qq) {
                    uint4 hv[4], lv[4];
                    #pragma unroll
                    for (int r = 0; r < 4; ++r) {
                        int u = (qq * 4 + r) * 64 + lt;   // 0..1023
                        int bb2 = u >> 5, kc = u & 31;
                        hv[r] = __ldcg((const uint4*)(ghi + (bb2 << 9) + 256 + kc * 8));
                        lv[r] = __ldcg((const uint4*)(glo + (bb2 << 9) + 256 + kc * 8));
                    }
                    #pragma unroll
                    for (int r = 0; r < 4; ++r) {
                        int u = (qq * 4 + r) * 64 + lt;
                        int bb2 = u >> 5, kc = u & 31;
                        *(uint4*)(sh_ahi + bb2 * LDK + 256 + kc * 8) = hv[r];
                        *(uint4*)(sh_alo + bb2 * LDK + 256 + kc * 8) = lv[r];
                    }
                }
            }
            __syncthreads();   // chunk1 ready; chunk0 mma done

            if (wid < 6) {
                #pragma unroll
                for (int kt = 16; kt < 32; ++kt) {
                    unsigned int ah[4], al[4];
                    LDSM4(ah, aBase + kt * 32);
                    LDSM4(al, aLoBase + kt * 32);
                    float* c = acc[kt & 3];
                    MMA_BF16(c, ah, Bh0[kt], Bh1[kt]);
                    MMA_BF16(c, ah, Bl0[kt], Bl1[kt]);
                    MMA_BF16(c, al, Bh0[kt], Bh1[kt]);
                }
                float c0 = acc[0][0] + acc[1][0] + acc[2][0] + acc[3][0];
                float c1 = acc[0][1] + acc[1][1] + acc[2][1] + acc[3][1];
                float c2 = acc[0][2] + acc[1][2] + acc[2][2] + acc[3][2];
                float c3 = acc[0][3] + acc[1][3] + acc[2][3] + acc[3][3];
                const int row = lane >> 2, cq = (lane & 3) << 1;
                float* gp = sh_gate + gate * 256 + (mt * 16 + row) * 8 + cq;
                gp[0] = c0; gp[1] = c1;
                gp[64] = c2; gp[65] = c3;
            }
            __syncthreads();
        }

        // ---- scalar epilogue: exact reference math ----
        const float iz = sh_gate[0 * 256 + b * 8 + c8] + bz;
        const float ir = sh_gate[1 * 256 + b * 8 + c8] + br;
        const float ic = sh_gate[2 * 256 + b * 8 + c8] + bh;

        const float zg = 1.f / (1.f + expf(-(x0 + iz)));
        const float rg = 1.f / (1.f + expf(-(x1 + ir)));
        const float hh = tanhf(x2 + rg * ic);
        const float hp = sh_hp[b * 8 + c8];
        const float hn = zg * hp + (1.f - zg) * hh;
        const float hsel = m ? hn : hp;
        const float yval = m ? hn : 0.f;
        sh_hp[b * 8 + c8] = hsel;

        // ---- critical path: publish h (bf16 hi/lo) + flag ----
        const size_t hdst = (size_t)((((t + 1) & 1) * 2 + dir)) << 14;
        __nv_bfloat16 h16 = __float2bfloat16(hsel);
        __nv_bfloat16 l16 = __float2bfloat16(hsel - __bfloat162float(h16));
        g_hhi[hdst + (b << 9) + col] = h16;
        g_hlo[hdst + (b << 9) + col] = l16;
        __syncthreads();
        if (tid == 0) {
            unsigned int v = (unsigned int)(flagBase + t + 1);
            asm volatile("st.release.gpu.global.u32 [%0], %1;"
                         :: "l"(myflag), "r"(v) : "memory");
        }

        // ---- off critical path: outputs ----
        const size_t yidx = ((size_t)b * T + tsrc) * 1024 + (dir << 9) + col;
        if (yhi) {
            __nv_bfloat16 yh16 = __float2bfloat16(yval);
            yhi[yidx] = yh16;
            ylo[yidx] = __float2bfloat16(yval - __bfloat162float(yh16));
        }
        if (y32) y32[yidx] = yval;
        if (writeHidden && t == T - 1)
            hiddenOut[(b << 10) + (dir << 9) + col] = hsel;
        if (maskWriter) {
            if ((t & 1) == 0) mprev = m;
            else nextmask[b * (T >> 1) + (t >> 1)] = (unsigned char)(mprev | m);
        }
    }
}

// ============================================================================
// Launch sequence (graph-capturable)
// ============================================================================
extern "C" void kernel_launch(void* const* d_in, const int* in_sizes, int n_in,
                              void* d_out, int out_size) {
    (void)in_sizes; (void)n_in; (void)out_size;
    const float* inputs = (const float*)d_in[0];

    const float *k_[4][2], *r_[4][2], *bi_[4][2];
    for (int l = 0; l < 4; ++l)
        for (int d = 0; d < 2; ++d) {
            int base = 3 + l * 6 + d * 3;
            k_[l][d]  = (const float*)d_in[base + 0];
            r_[l][d]  = (const float*)d_in[base + 1];
            bi_[l][d] = (const float*)d_in[base + 2];
        }

    float *xzf, *xzb;
    unsigned char* mk;
    __nv_bfloat16 *whi, *wlo, *inhi, *inlo, *yh0, *yl0, *yh1, *yl1;
    cudaGetSymbolAddress((void**)&xzf, g_xzf);
    cudaGetSymbolAddress((void**)&xzb, g_xzb);
    cudaGetSymbolAddress((void**)&mk, g_mask);
    cudaGetSymbolAddress((void**)&whi, g_whi);
    cudaGetSymbolAddress((void**)&wlo, g_wlo);
    cudaGetSymbolAddress((void**)&inhi, g_inhi);
    cudaGetSymbolAddress((void**)&inlo, g_inlo);
    cudaGetSymbolAddress((void**)&yh0, g_yh0);
    cudaGetSymbolAddress((void**)&yl0, g_yl0);
    cudaGetSymbolAddress((void**)&yh1, g_yh1);
    cudaGetSymbolAddress((void**)&yl1, g_yl1);

    cudaFuncSetAttribute(gru_rec_kernel,
                         cudaFuncAttributeMaxDynamicSharedMemorySize, REC_SMEM);

    float* outp = (float*)d_out;
    float* hid  = outp + (size_t)32 * 128 * 1024;

    prep_kernel<<<2048, 256>>>(inputs, k_[0][0], k_[0][1], k_[1][0], k_[1][1],
                               k_[2][0], k_[2][1], k_[3][0], k_[3][1]);

    const int Ts[4]   = {1024, 512, 256, 128};
    const int Ks[4]   = {240, 2048, 2048, 2048};
    const int ldas[4] = {240, 2048, 2048, 2048};
    const int woff[4][2] = {{0, WSZ0},
                            {2 * WSZ0, 2 * WSZ0 + WSZ1},
                            {2 * WSZ0 + 2 * WSZ1, 2 * WSZ0 + 3 * WSZ1},
                            {2 * WSZ0 + 4 * WSZ1, 2 * WSZ0 + 5 * WSZ1}};
    const int moff[4]  = {0, 32768, 49152, 57344};
    const int fbase[4] = {0, 1024, 1536, 1792};

    const __nv_bfloat16* Ah[4] = {inhi, yh0, yh1, yh0};
    const __nv_bfloat16* Al[4] = {inlo, yl0, yl1, yl0};
    __nv_bfloat16* Yh[4] = {yh0, yh1, yh0, nullptr};
    __nv_bfloat16* Yl[4] = {yl0, yl1, yl0, nullptr};
    float* Y32[4] = {nullptr, nullptr, nullptr, outp};

    for (int l = 0; l < 4; ++l) {
        const int T = Ts[l], K = Ks[l];
        const int rows = 32 * T;

        dim3 grid(6, rows / 128, 2);
        gemm_xz<<<grid, 256>>>(Ah[l], Al[l], ldas[l],
                               whi + woff[l][0], wlo + woff[l][0],
                               whi + woff[l][1], wlo + woff[l][1],
                               bi_[l][0], bi_[l][1],
                               xzf, xzb, K, T, mk + moff[l]);

        gru_rec_kernel<<<128, REC_THREADS, REC_SMEM>>>(
            xzf, xzb, r_[l][0], r_[l][1], bi_[l][0], bi_[l][1],
            mk + moff[l], Y32[l], Yh[l], Yl[l],
            (l < 3) ? (mk + moff[l + 1]) : nullptr,
            T, fbase[l], (l == 3) ? 1 : 0, hid);
    }
}

// round 9
// speedup vs baseline: 1.1441x; 1.0164x over previous
#include <cuda_runtime.h>
#include <cuda_bf16.h>
#include <cstdint>

// ============================================================================
// 4-layer pyramidal BiGRU. B=32, H=512, 3H=1536.
// Layers l=0..3: T = 1024,512,256,128 ; din = 240,2048,2048,2048
// ============================================================================

#define REC_THREADS 256

// ---------------- static device scratch ----------------
__device__ float g_xzf[50331648];                 // [32][1024][1536] max
__device__ float g_xzb[50331648];
__device__ unsigned int g_flag[2 * 512];          // [dir][64 ctas] stride-8
__device__ unsigned char g_mask[65536];           // per-layer offsets
__device__ __nv_bfloat16 g_whi[19611648], g_wlo[19611648];
__device__ __nv_bfloat16 g_inhi[7864320],  g_inlo[7864320];
__device__ __nv_bfloat16 g_yh0[33554432],  g_yl0[33554432];
__device__ __nv_bfloat16 g_yh1[16777216],  g_yl1[16777216];
__device__ __nv_bfloat16 g_hhi[4 * 16384], g_hlo[4 * 16384];

// ---------------- mma / ldmatrix ----------------
#define MMA_BF16(c, a, b0, b1)                                              \
    asm volatile("mma.sync.aligned.m16n8k16.row.col.f32.bf16.bf16.f32 "     \
        "{%0,%1,%2,%3}, {%4,%5,%6,%7}, {%8,%9}, {%0,%1,%2,%3};"             \
        : "+f"((c)[0]), "+f"((c)[1]), "+f"((c)[2]), "+f"((c)[3])            \
        : "r"((a)[0]), "r"((a)[1]), "r"((a)[2]), "r"((a)[3]),               \
          "r"(b0), "r"(b1))

#define LDSM4(R, addr)                                                      \
    asm volatile("ldmatrix.sync.aligned.m8n8.x4.shared.b16 "                \
        "{%0,%1,%2,%3}, [%4];"                                              \
        : "=r"((R)[0]), "=r"((R)[1]), "=r"((R)[2]), "=r"((R)[3])            \
        : "r"(addr))

#define LDSM4T(R, addr)                                                     \
    asm volatile("ldmatrix.sync.aligned.m8n8.x4.trans.shared.b16 "          \
        "{%0,%1,%2,%3}, [%4];"                                              \
        : "=r"((R)[0]), "=r"((R)[1]), "=r"((R)[2]), "=r"((R)[3])            \
        : "r"(addr))

__device__ __forceinline__ unsigned int smaddr(const void* p) {
    return (unsigned int)__cvta_generic_to_shared(p);
}
__device__ __forceinline__ unsigned int bfpack(float a, float b) {
    __nv_bfloat162 h = __floats2bfloat162_rn(a, b);
    return *reinterpret_cast<unsigned int*>(&h);
}

// ============================================================================
// prep kernel: convert 8 weight matrices + layer-0 input to bf16 hi/lo,
// compute layer-0 mask, zero flags.
// ============================================================================
__device__ __forceinline__ void cvt4(float4 v, uint2& hi, uint2& lo) {
    __nv_bfloat162 h0 = __floats2bfloat162_rn(v.x, v.y);
    __nv_bfloat162 h1 = __floats2bfloat162_rn(v.z, v.w);
    float2 f0 = __bfloat1622float2(h0);
    float2 f1 = __bfloat1622float2(h1);
    __nv_bfloat162 l0 = __floats2bfloat162_rn(v.x - f0.x, v.y - f0.y);
    __nv_bfloat162 l1 = __floats2bfloat162_rn(v.z - f1.x, v.w - f1.y);
    hi.x = *(unsigned int*)&h0; hi.y = *(unsigned int*)&h1;
    lo.x = *(unsigned int*)&l0; lo.y = *(unsigned int*)&l1;
}

#define WSZ0 368640
#define WSZ1 3145728

__global__ void prep_kernel(const float* __restrict__ in,
                            const float* w0, const float* w1, const float* w2,
                            const float* w3, const float* w4, const float* w5,
                            const float* w6, const float* w7) {
    const float* ws[8] = {w0, w1, w2, w3, w4, w5, w6, w7};
    const int sz[8]  = {WSZ0, WSZ0, WSZ1, WSZ1, WSZ1, WSZ1, WSZ1, WSZ1};
    const int off[8] = {0, WSZ0, 2 * WSZ0, 2 * WSZ0 + WSZ1, 2 * WSZ0 + 2 * WSZ1,
                        2 * WSZ0 + 3 * WSZ1, 2 * WSZ0 + 4 * WSZ1, 2 * WSZ0 + 5 * WSZ1};
    const int gid = blockIdx.x * blockDim.x + threadIdx.x;
    const int stride = gridDim.x * blockDim.x;

    #pragma unroll 1
    for (int w = 0; w < 8; ++w) {
        const float4* W = (const float4*)ws[w];
        uint2* hi = (uint2*)(g_whi + off[w]);
        uint2* lo = (uint2*)(g_wlo + off[w]);
        int n4 = sz[w] >> 2;
        for (int i = gid; i < n4; i += stride) {
            uint2 h, l; cvt4(__ldg(W + i), h, l);
            hi[i] = h; lo[i] = l;
        }
    }
    {
        const float4* X = (const float4*)in;
        uint2* hi = (uint2*)g_inhi; uint2* lo = (uint2*)g_inlo;
        for (int i = gid; i < (7864320 >> 2); i += stride) {
            uint2 h, l; cvt4(__ldg(X + i), h, l);
            hi[i] = h; lo[i] = l;
        }
    }
    for (int r = gid; r < 32768; r += stride) {
        const float4* p = (const float4*)(in + (size_t)r * 240);
        bool any = false;
        for (int i = 0; i < 60; ++i) {
            float4 v = __ldg(p + i);
            any = any | (v.x != 0.f) | (v.y != 0.f) | (v.z != 0.f) | (v.w != 0.f);
            if (any) break;
        }
        g_mask[r] = any ? 1 : 0;
    }
    for (int i = gid; i < 2 * 512; i += stride) g_flag[i] = 0u;
}

// ============================================================================
// Input-projection GEMM: bf16 hi/lo, mma.sync 128x256x16 tile, fwd+bwd via
// grid.z, masked-tile skip. Double-buffered SMEM with REGISTER prefetch and
// ONE __syncthreads per k-tile (writes always target the non-read buffer).
// ============================================================================
#define GA 3072
#define GW 4224
#define G_STAGE ((2 * GA + 2 * GW) * 2)   // 29184 bytes
#define GSMEM (2 * G_STAGE)               // 58368 bytes

__global__ void __launch_bounds__(256, 1) gemm_xz(
    const __nv_bfloat16* __restrict__ Ahi, const __nv_bfloat16* __restrict__ Alo,
    int lda,
    const __nv_bfloat16* __restrict__ WhiF, const __nv_bfloat16* __restrict__ WloF,
    const __nv_bfloat16* __restrict__ WhiB, const __nv_bfloat16* __restrict__ WloB,
    const float* __restrict__ biasF, const float* __restrict__ biasB,
    float* __restrict__ Cf, float* __restrict__ Cb,
    int K, int Tcur, const unsigned char* __restrict__ mask) {
    extern __shared__ __align__(16) char gsm[];

    const int dir = blockIdx.z;
    const int rev = dir;
    const __nv_bfloat16* Whi = dir ? WhiB : WhiF;
    const __nv_bfloat16* Wlo = dir ? WloB : WloF;
    const float* bias = dir ? biasB : biasF;
    float* C = dir ? Cb : Cf;

    const int tid  = threadIdx.x;
    const int lane = tid & 31, wid = tid >> 5;
    const int g = lane >> 2, t4 = lane & 3;
    const int warpM = wid & 3, warpN = wid >> 2;
    const int m0 = blockIdx.y << 7, n0 = blockIdx.x << 8;

    {
        const int b  = m0 / Tcur;
        const int t0 = m0 - b * Tcur;
        const int ttmin = rev ? (Tcur - 128 - t0) : t0;
        if (mask[b * Tcur + ttmin] == 0) return;
    }

    const int ar = tid >> 1;
    const int ak = (tid & 1) << 3;
    const int wk = tid >> 4;
    const int wc = (tid & 15) << 4;

    const __nv_bfloat16 *pAh, *pAl;
    {
        int m  = m0 + ar;
        int bi = m / Tcur;
        int t  = m - bi * Tcur;
        int tt = rev ? (Tcur - 1 - t) : t;
        size_t base = ((size_t)bi * Tcur + tt) * lda + ak;
        pAh = Ahi + base; pAl = Alo + base;
    }
    const __nv_bfloat16* pWh = Whi + (size_t)wk * 1536 + n0 + wc;
    const __nv_bfloat16* pWl = Wlo + (size_t)wk * 1536 + n0 + wc;

    // byte offsets within a stage
    const unsigned int smBase = smaddr(gsm);
    const unsigned int dA_hi = (unsigned)((ar * 24 + ak) * 2);
    const unsigned int dA_lo = dA_hi + GA * 2;
    const unsigned int dW_hi = (unsigned)((2 * GA + wk * 264 + wc) * 2);
    const unsigned int dW_lo = dW_hi + GW * 2;

    const int aRowL = warpM * 32 + (lane & 15);
    const int aKofL = (lane & 16) >> 1;
    const unsigned int oAhi = (unsigned)((aRowL * 24 + aKofL) * 2);
    const unsigned int oAlo = oAhi + GA * 2;
    const int bCol = warpN * 128 + ((lane & 16) >> 1);
    const unsigned int oBhi = (unsigned)((2 * GA + (lane & 15) * 264 + bCol) * 2);
    const unsigned int oBlo = oBhi + GW * 2;

    float c_[2][16][4];
    #pragma unroll
    for (int mt = 0; mt < 2; ++mt)
        #pragma unroll
        for (int nt = 0; nt < 16; ++nt)
            #pragma unroll
            for (int i = 0; i < 4; ++i) c_[mt][nt][i] = 0.f;

    const int NT = K >> 4;
    uint4 rAh = *(const uint4*)pAh;
    uint4 rAl = *(const uint4*)pAl;
    uint4 rWh0 = *(const uint4*)pWh;
    uint4 rWh1 = *(const uint4*)(pWh + 8);
    uint4 rWl0 = *(const uint4*)pWl;
    uint4 rWl1 = *(const uint4*)(pWl + 8);

    for (int kt = 0; kt < NT; ++kt) {
        const unsigned int sb = smBase + (kt & 1) * G_STAGE;
        *(uint4*)(gsm + (kt & 1) * G_STAGE + dA_hi) = rAh;
        *(uint4*)(gsm + (kt & 1) * G_STAGE + dA_lo) = rAl;
        *(uint4*)(gsm + (kt & 1) * G_STAGE + dW_hi)      = rWh0;
        *(uint4*)(gsm + (kt & 1) * G_STAGE + dW_hi + 16) = rWh1;
        *(uint4*)(gsm + (kt & 1) * G_STAGE + dW_lo)      = rWl0;
        *(uint4*)(gsm + (kt & 1) * G_STAGE + dW_lo + 16) = rWl1;
        __syncthreads();

        if (kt + 1 < NT) {
            int k0 = (kt + 1) << 4;
            rAh = *(const uint4*)(pAh + k0);
            rAl = *(const uint4*)(pAl + k0);
            const __nv_bfloat16* qh = pWh + (size_t)k0 * 1536;
            const __nv_bfloat16* ql = pWl + (size_t)k0 * 1536;
            rWh0 = *(const uint4*)qh; rWh1 = *(const uint4*)(qh + 8);
            rWl0 = *(const uint4*)ql; rWl1 = *(const uint4*)(ql + 8);
        }

        unsigned int afh[2][4], afl[2][4];
        #pragma unroll
        for (int mt = 0; mt < 2; ++mt) {
            LDSM4(afh[mt], sb + oAhi + mt * 768);
            LDSM4(afl[mt], sb + oAlo + mt * 768);
        }

        #pragma unroll
        for (int p = 0; p < 8; ++p) {
            unsigned int bh[4], bl[4];
            LDSM4T(bh, sb + oBhi + p * 32);
            LDSM4T(bl, sb + oBlo + p * 32);
            #pragma unroll
            for (int s = 0; s < 2; ++s) {
                const int nt = 2 * p + s;
                #pragma unroll
                for (int mt = 0; mt < 2; ++mt) {
                    MMA_BF16(c_[mt][nt], afh[mt], bh[2 * s], bh[2 * s + 1]);
                    MMA_BF16(c_[mt][nt], afh[mt], bl[2 * s], bl[2 * s + 1]);
                    MMA_BF16(c_[mt][nt], afl[mt], bh[2 * s], bh[2 * s + 1]);
                }
            }
        }
        // no trailing sync: next iteration writes the OTHER buffer
    }

    #pragma unroll
    for (int nt = 0; nt < 16; ++nt) {
        int col = n0 + warpN * 128 + nt * 8 + t4 * 2;
        float bx = __ldg(bias + col);
        float by = __ldg(bias + col + 1);
        #pragma unroll
        for (int mt = 0; mt < 2; ++mt) {
            int r = m0 + warpM * 32 + mt * 16 + g;
            float2 o0 = {c_[mt][nt][0] + bx, c_[mt][nt][1] + by};
            float2 o1 = {c_[mt][nt][2] + bx, c_[mt][nt][3] + by};
            *(float2*)(C + (size_t)r * 1536 + col)       = o0;
            *(float2*)(C + (size_t)(r + 8) * 1536 + col) = o1;
        }
    }
}

// ============================================================================
// Recurrence on tensor cores (round-6 base + SMSP-balanced mma).
//   Units u=(gate,mt), u=0..5. Warps 0-3: units 0-3, full K (32 kt).
//   Unit 4 (g2,mt0): warp 4 kt 0-15, warp 6 kt 16-31.
//   Unit 5 (g2,mt1): warp 5 kt 0-15, warp 7 kt 16-31.
//   -> every SMSP issues 144 mma/step (was 192 on SMSP 0/1).
//   Gate-2 totals combine two partials (slot 2 + slot 3) in the epilogue.
// SMEM: ahi[32][520] | alo[32][520] bf16 | gate[4][32][8] f32 | hp[256]
// ============================================================================
#define LDK 520
#define REC_SMEM (2 * 32 * LDK * 2 + 4 * 256 * 4 + 256 * 4)

__global__ void __launch_bounds__(REC_THREADS, 1) gru_rec_kernel(
    const float* __restrict__ xzf, const float* __restrict__ xzb,
    const float* __restrict__ rkf, const float* __restrict__ rkb,
    const float* __restrict__ bf,  const float* __restrict__ bb,
    const unsigned char* __restrict__ mask,
    float* __restrict__ y32,
    __nv_bfloat16* __restrict__ yhi, __nv_bfloat16* __restrict__ ylo,
    unsigned char* __restrict__ nextmask,
    int T, int flagBase, int writeHidden, float* __restrict__ hiddenOut) {
    extern __shared__ __align__(16) char smraw[];
    __nv_bfloat16* sh_ahi = (__nv_bfloat16*)smraw;                // [32][520]
    __nv_bfloat16* sh_alo = sh_ahi + 32 * LDK;                    // [32][520]
    float* sh_gate = (float*)(sh_alo + 32 * LDK);                 // [4][32][8]
    float* sh_hp   = sh_gate + 4 * 256;                           // [256]

    const int tid  = threadIdx.x;
    const int lane = tid & 31, wid = tid >> 5;
    const int dir = blockIdx.x >> 6;
    const int j   = blockIdx.x & 63;
    const int cb  = j << 3;
    const int b   = tid >> 3;
    const int c8  = tid & 7;
    const int col = cb + c8;

    const float* xz = dir ? xzb : xzf;
    const float* rk = dir ? rkb : rkf;
    const float* bi = (dir ? bb : bf) + 1536;   // b[1]

    for (int i = tid; i < 4 * 256 + 256; i += REC_THREADS) sh_gate[i] = 0.f;

    // ---- unit assignment ----
    const int unit = (wid < 6) ? wid : (wid - 2);   // 0..5
    const int gate = unit >> 1;                     // 0..2
    const int mt   = unit & 1;                      // 0..1
    const int ktbase = (wid < 6) ? 0 : 16;          // warps 6,7 take high K
    const int nkt = (wid < 4) ? 32 : 16;
    const int t4   = lane & 3;
    const int gcol = lane >> 2;                     // 0..7

    // ---- B-fragment preload (all 8 warps) ----
    unsigned int Bh0[32], Bh1[32], Bl0[32], Bl1[32];
    {
        const float* wcolp = rk + gate * 512 + cb + gcol;
        #pragma unroll 1
        for (int q = 0; q < nkt; ++q) {
            int k0 = (ktbase + q) * 16 + t4 * 2;
            float w00 = __ldg(wcolp + (size_t)(k0)     * 1536);
            float w01 = __ldg(wcolp + (size_t)(k0 + 1) * 1536);
            float w10 = __ldg(wcolp + (size_t)(k0 + 8) * 1536);
            float w11 = __ldg(wcolp + (size_t)(k0 + 9) * 1536);
            __nv_bfloat16 h00 = __float2bfloat16(w00), h01 = __float2bfloat16(w01);
            __nv_bfloat16 h10 = __float2bfloat16(w10), h11 = __float2bfloat16(w11);
            Bh0[q] = ((unsigned)*(unsigned short*)&h01 << 16) | *(unsigned short*)&h00;
            Bh1[q] = ((unsigned)*(unsigned short*)&h11 << 16) | *(unsigned short*)&h10;
            Bl0[q] = bfpack(w00 - __bfloat162float(h00), w01 - __bfloat162float(h01));
            Bl1[q] = bfpack(w10 - __bfloat162float(h10), w11 - __bfloat162float(h11));
        }
    }
    const float bz = __ldg(bi + col);
    const float br = __ldg(bi + 512 + col);
    const float bh = __ldg(bi + 1024 + col);
    __syncthreads();

    // ldmatrix lane address (A = h matrix, rows = batch); pre-offset by ktbase
    const unsigned int aBase = smaddr(sh_ahi) +
        (unsigned)(((mt * 16 + (lane & 15)) * LDK + ((lane >> 4) << 3)) * 2) +
        (unsigned)(ktbase * 32);
    const unsigned int aLoBase = aBase + 32 * LDK * 2;
    const int gslot = (wid < 6) ? gate : 3;

    unsigned int* myflag = g_flag + dir * 512 + j * 8;
    const unsigned int* pollflag = g_flag + dir * 512 + (tid & 63) * 8;
    const bool maskWriter = (nextmask != nullptr) && (dir == 0) && (j == 0) && (c8 == 0);
    unsigned char mprev = 0;

    for (int t = 0; t < T; ++t) {
        const int tsrc = dir ? (T - 1 - t) : t;
        const size_t xoff = ((size_t)b * T + t) * 1536;
        const float x0 = __ldg(xz + xoff + col);
        const float x1 = __ldg(xz + xoff + 512 + col);
        const float x2 = __ldg(xz + xoff + 1024 + col);
        const unsigned char m = mask[b * T + tsrc];

        if (t > 0) {
            // ---- wait for step t-1 of all CTAs in this direction ----
            if (tid < 64) {
                unsigned int v;
                unsigned int target = (unsigned int)(flagBase + t);
                do {
                    asm volatile("ld.acquire.gpu.global.u32 %0, [%1];"
                                 : "=r"(v) : "l"(pollflag) : "memory");
                } while (v < target);
            }
            __syncthreads();

            // ---- stage h (bf16 hi/lo) into SMEM (round-6 proven loop) ----
            const size_t hsrc = (size_t)(((t & 1) * 2 + dir)) << 14;
            const __nv_bfloat16* ghi = g_hhi + hsrc;
            const __nv_bfloat16* glo = g_hlo + hsrc;
            #pragma unroll
            for (int q = 0; q < 8; ++q) {
                int v = q * 256 + tid;
                int bb2 = v >> 6, kc = v & 63;
                uint4 hv = __ldcg((const uint4*)(ghi + (bb2 << 9) + kc * 8));
                uint4 lv = __ldcg((const uint4*)(glo + (bb2 << 9) + kc * 8));
                *(uint4*)(sh_ahi + bb2 * LDK + kc * 8) = hv;
                *(uint4*)(sh_alo + bb2 * LDK + kc * 8) = lv;
            }
            __syncthreads();

            // ---- balanced mma: warps 0-3 full K, warps 4-7 half K ----
            float acc[4][4];
            #pragma unroll
            for (int i = 0; i < 4; ++i)
                #pragma unroll
                for (int q = 0; q < 4; ++q) acc[i][q] = 0.f;

            if (wid < 4) {
                #pragma unroll
                for (int q = 0; q < 32; ++q) {
                    unsigned int ah[4], al[4];
                    LDSM4(ah, aBase + q * 32);
                    LDSM4(al, aLoBase + q * 32);
                    float* c = acc[q & 3];
                    MMA_BF16(c, ah, Bh0[q], Bh1[q]);
                    MMA_BF16(c, ah, Bl0[q], Bl1[q]);
                    MMA_BF16(c, al, Bh0[q], Bh1[q]);
                }
            } else {
                #pragma unroll
                for (int q = 0; q < 16; ++q) {
                    unsigned int ah[4], al[4];
                    LDSM4(ah, aBase + q * 32);
                    LDSM4(al, aLoBase + q * 32);
                    float* c = acc[q & 3];
                    MMA_BF16(c, ah, Bh0[q], Bh1[q]);
                    MMA_BF16(c, ah, Bl0[q], Bl1[q]);
                    MMA_BF16(c, al, Bh0[q], Bh1[q]);
                }
            }
            float c0 = acc[0][0] + acc[1][0] + acc[2][0] + acc[3][0];
            float c1 = acc[0][1] + acc[1][1] + acc[2][1] + acc[3][1];
            float c2 = acc[0][2] + acc[1][2] + acc[2][2] + acc[3][2];
            float c3 = acc[0][3] + acc[1][3] + acc[2][3] + acc[3][3];
            const int row = lane >> 2, cq = (lane & 3) << 1;
            float* gp = sh_gate + gslot * 256 + (mt * 16 + row) * 8 + cq;
            gp[0] = c0; gp[1] = c1;
            gp[64] = c2; gp[65] = c3;
            __syncthreads();
        }

        // ---- scalar epilogue: exact reference math ----
        const int gidx = b * 8 + c8;
        const float iz = sh_gate[0 * 256 + gidx] + bz;
        const float ir = sh_gate[1 * 256 + gidx] + br;
        const float ic = sh_gate[2 * 256 + gidx] + sh_gate[3 * 256 + gidx] + bh;

        const float zg = 1.f / (1.f + expf(-(x0 + iz)));
        const float rg = 1.f / (1.f + expf(-(x1 + ir)));
        const float hh = tanhf(x2 + rg * ic);
        const float hp = sh_hp[gidx];
        const float hn = zg * hp + (1.f - zg) * hh;
        const float hsel = m ? hn : hp;
        const float yval = m ? hn : 0.f;
        sh_hp[gidx] = hsel;

        // ---- critical path: publish h (bf16 hi/lo) + flag ----
        const size_t hdst = (size_t)((((t + 1) & 1) * 2 + dir)) << 14;
        __nv_bfloat16 h16 = __float2bfloat16(hsel);
        __nv_bfloat16 l16 = __float2bfloat16(hsel - __bfloat162float(h16));
        g_hhi[hdst + (b << 9) + col] = h16;
        g_hlo[hdst + (b << 9) + col] = l16;
        __syncthreads();
        if (tid == 0) {
            unsigned int v = (unsigned int)(flagBase + t + 1);
            asm volatile("st.release.gpu.global.u32 [%0], %1;"
                         :: "l"(myflag), "r"(v) : "memory");
        }

        // ---- off critical path: outputs ----
        const size_t yidx = ((size_t)b * T + tsrc) * 1024 + (dir << 9) + col;
        if (yhi) {
            __nv_bfloat16 yh16 = __float2bfloat16(yval);
            yhi[yidx] = yh16;
            ylo[yidx] = __float2bfloat16(yval - __bfloat162float(yh16));
        }
        if (y32) y32[yidx] = yval;
        if (writeHidden && t == T - 1)
            hiddenOut[(b << 10) + (dir << 9) + col] = hsel;
        if (maskWriter) {
            if ((t & 1) == 0) mprev = m;
            else nextmask[b * (T >> 1) + (t >> 1)] = (unsigned char)(mprev | m);
        }
    }
}

// ============================================================================
// Launch sequence (graph-capturable)
// ============================================================================
extern "C" void kernel_launch(void* const* d_in, const int* in_sizes, int n_in,
                              void* d_out, int out_size) {
    (void)in_sizes; (void)n_in; (void)out_size;
    const float* inputs = (const float*)d_in[0];

    const float *k_[4][2], *r_[4][2], *bi_[4][2];
    for (int l = 0; l < 4; ++l)
        for (int d = 0; d < 2; ++d) {
            int base = 3 + l * 6 + d * 3;
            k_[l][d]  = (const float*)d_in[base + 0];
            r_[l][d]  = (const float*)d_in[base + 1];
            bi_[l][d] = (const float*)d_in[base + 2];
        }

    float *xzf, *xzb;
    unsigned char* mk;
    __nv_bfloat16 *whi, *wlo, *inhi, *inlo, *yh0, *yl0, *yh1, *yl1;
    cudaGetSymbolAddress((void**)&xzf, g_xzf);
    cudaGetSymbolAddress((void**)&xzb, g_xzb);
    cudaGetSymbolAddress((void**)&mk, g_mask);
    cudaGetSymbolAddress((void**)&whi, g_whi);
    cudaGetSymbolAddress((void**)&wlo, g_wlo);
    cudaGetSymbolAddress((void**)&inhi, g_inhi);
    cudaGetSymbolAddress((void**)&inlo, g_inlo);
    cudaGetSymbolAddress((void**)&yh0, g_yh0);
    cudaGetSymbolAddress((void**)&yl0, g_yl0);
    cudaGetSymbolAddress((void**)&yh1, g_yh1);
    cudaGetSymbolAddress((void**)&yl1, g_yl1);

    cudaFuncSetAttribute(gru_rec_kernel,
                         cudaFuncAttributeMaxDynamicSharedMemorySize, REC_SMEM);
    cudaFuncSetAttribute(gemm_xz,
                         cudaFuncAttributeMaxDynamicSharedMemorySize, GSMEM);

    float* outp = (float*)d_out;
    float* hid  = outp + (size_t)32 * 128 * 1024;

    prep_kernel<<<2048, 256>>>(inputs, k_[0][0], k_[0][1], k_[1][0], k_[1][1],
                               k_[2][0], k_[2][1], k_[3][0], k_[3][1]);

    const int Ts[4]   = {1024, 512, 256, 128};
    const int Ks[4]   = {240, 2048, 2048, 2048};
    const int ldas[4] = {240, 2048, 2048, 2048};
    const int woff[4][2] = {{0, WSZ0},
                            {2 * WSZ0, 2 * WSZ0 + WSZ1},
                            {2 * WSZ0 + 2 * WSZ1, 2 * WSZ0 + 3 * WSZ1},
                            {2 * WSZ0 + 4 * WSZ1, 2 * WSZ0 + 5 * WSZ1}};
    const int moff[4]  = {0, 32768, 49152, 57344};
    const int fbase[4] = {0, 1024, 1536, 1792};

    const __nv_bfloat16* Ah[4] = {inhi, yh0, yh1, yh0};
    const __nv_bfloat16* Al[4] = {inlo, yl0, yl1, yl0};
    __nv_bfloat16* Yh[4] = {yh0, yh1, yh0, nullptr};
    __nv_bfloat16* Yl[4] = {yl0, yl1, yl0, nullptr};
    float* Y32[4] = {nullptr, nullptr, nullptr, outp};

    for (int l = 0; l < 4; ++l) {
        const int T = Ts[l], K = Ks[l];
        const int rows = 32 * T;

        dim3 grid(6, rows / 128, 2);
        gemm_xz<<<grid, 256, GSMEM>>>(Ah[l], Al[l], ldas[l],
                               whi + woff[l][0], wlo + woff[l][0],
                               whi + woff[l][1], wlo + woff[l][1],
                               bi_[l][0], bi_[l][1],
                               xzf, xzb, K, T, mk + moff[l]);

        gru_rec_kernel<<<128, REC_THREADS, REC_SMEM>>>(
            xzf, xzb, r_[l][0], r_[l][1], bi_[l][0], bi_[l][1],
            mk + moff[l], Y32[l], Yh[l], Yl[l],
            (l < 3) ? (mk + moff[l + 1]) : nullptr,
            T, fbase[l], (l == 3) ? 1 : 0, hid);
    }
}

// round 10
// speedup vs baseline: 1.2183x; 1.0649x over previous
#include <cuda_runtime.h>
#include <cuda_bf16.h>
#include <cstdint>

// ============================================================================
// 4-layer pyramidal BiGRU. B=32, H=512, 3H=1536.
// Layers l=0..3: T = 1024,512,256,128 ; din = 240,2048,2048,2048
// ============================================================================

#define REC_THREADS 256

// ---------------- static device scratch ----------------
__device__ float g_xzf[50331648];                 // [32][1024][1536] max
__device__ float g_xzb[50331648];
__device__ unsigned int g_flag[2 * 512];          // [dir][64 ctas] stride-8
__device__ unsigned char g_mask[65536];           // per-layer offsets
__device__ __nv_bfloat16 g_whi[19611648], g_wlo[19611648];
__device__ __nv_bfloat16 g_inhi[7864320],  g_inlo[7864320];
__device__ __nv_bfloat16 g_yh0[33554432],  g_yl0[33554432];
__device__ __nv_bfloat16 g_yh1[16777216],  g_yl1[16777216];
__device__ __nv_bfloat16 g_hhi[4 * 16384], g_hlo[4 * 16384];

// ---------------- mma / ldmatrix ----------------
#define MMA_BF16(c, a, b0, b1)                                              \
    asm volatile("mma.sync.aligned.m16n8k16.row.col.f32.bf16.bf16.f32 "     \
        "{%0,%1,%2,%3}, {%4,%5,%6,%7}, {%8,%9}, {%0,%1,%2,%3};"             \
        : "+f"((c)[0]), "+f"((c)[1]), "+f"((c)[2]), "+f"((c)[3])            \
        : "r"((a)[0]), "r"((a)[1]), "r"((a)[2]), "r"((a)[3]),               \
          "r"(b0), "r"(b1))

#define LDSM4(R, addr)                                                      \
    asm volatile("ldmatrix.sync.aligned.m8n8.x4.shared.b16 "                \
        "{%0,%1,%2,%3}, [%4];"                                              \
        : "=r"((R)[0]), "=r"((R)[1]), "=r"((R)[2]), "=r"((R)[3])            \
        : "r"(addr))

#define LDSM4T(R, addr)                                                     \
    asm volatile("ldmatrix.sync.aligned.m8n8.x4.trans.shared.b16 "          \
        "{%0,%1,%2,%3}, [%4];"                                              \
        : "=r"((R)[0]), "=r"((R)[1]), "=r"((R)[2]), "=r"((R)[3])            \
        : "r"(addr))

__device__ __forceinline__ unsigned int smaddr(const void* p) {
    return (unsigned int)__cvta_generic_to_shared(p);
}
__device__ __forceinline__ unsigned int bfpack(float a, float b) {
    __nv_bfloat162 h = __floats2bfloat162_rn(a, b);
    return *reinterpret_cast<unsigned int*>(&h);
}

// ============================================================================
// prep kernel: convert 8 weight matrices + layer-0 input to bf16 hi/lo,
// compute layer-0 mask, zero flags.
// ============================================================================
__device__ __forceinline__ void cvt4(float4 v, uint2& hi, uint2& lo) {
    __nv_bfloat162 h0 = __floats2bfloat162_rn(v.x, v.y);
    __nv_bfloat162 h1 = __floats2bfloat162_rn(v.z, v.w);
    float2 f0 = __bfloat1622float2(h0);
    float2 f1 = __bfloat1622float2(h1);
    __nv_bfloat162 l0 = __floats2bfloat162_rn(v.x - f0.x, v.y - f0.y);
    __nv_bfloat162 l1 = __floats2bfloat162_rn(v.z - f1.x, v.w - f1.y);
    hi.x = *(unsigned int*)&h0; hi.y = *(unsigned int*)&h1;
    lo.x = *(unsigned int*)&l0; lo.y = *(unsigned int*)&l1;
}

#define WSZ0 368640
#define WSZ1 3145728

__global__ void prep_kernel(const float* __restrict__ in,
                            const float* w0, const float* w1, const float* w2,
                            const float* w3, const float* w4, const float* w5,
                            const float* w6, const float* w7) {
    const float* ws[8] = {w0, w1, w2, w3, w4, w5, w6, w7};
    const int sz[8]  = {WSZ0, WSZ0, WSZ1, WSZ1, WSZ1, WSZ1, WSZ1, WSZ1};
    const int off[8] = {0, WSZ0, 2 * WSZ0, 2 * WSZ0 + WSZ1, 2 * WSZ0 + 2 * WSZ1,
                        2 * WSZ0 + 3 * WSZ1, 2 * WSZ0 + 4 * WSZ1, 2 * WSZ0 + 5 * WSZ1};
    const int gid = blockIdx.x * blockDim.x + threadIdx.x;
    const int stride = gridDim.x * blockDim.x;

    #pragma unroll 1
    for (int w = 0; w < 8; ++w) {
        const float4* W = (const float4*)ws[w];
        uint2* hi = (uint2*)(g_whi + off[w]);
        uint2* lo = (uint2*)(g_wlo + off[w]);
        int n4 = sz[w] >> 2;
        for (int i = gid; i < n4; i += stride) {
            uint2 h, l; cvt4(__ldg(W + i), h, l);
            hi[i] = h; lo[i] = l;
        }
    }
    {
        const float4* X = (const float4*)in;
        uint2* hi = (uint2*)g_inhi; uint2* lo = (uint2*)g_inlo;
        for (int i = gid; i < (7864320 >> 2); i += stride) {
            uint2 h, l; cvt4(__ldg(X + i), h, l);
            hi[i] = h; lo[i] = l;
        }
    }
    for (int r = gid; r < 32768; r += stride) {
        const float4* p = (const float4*)(in + (size_t)r * 240);
        bool any = false;
        for (int i = 0; i < 60; ++i) {
            float4 v = __ldg(p + i);
            any = any | (v.x != 0.f) | (v.y != 0.f) | (v.z != 0.f) | (v.w != 0.f);
            if (any) break;
        }
        g_mask[r] = any ? 1 : 0;
    }
    for (int i = gid; i < 2 * 512; i += stride) g_flag[i] = 0u;
}

// ============================================================================
// Input-projection GEMM: bf16 hi/lo, mma.sync, tile 128x128x16,
// TWO CTAs PER SM (launch_bounds(256,2)) so one CTA's mma covers the other's
// fill/sync bubble. Register prefetch, single SMEM buffer (proven pattern).
// grid = (12, rows/128, 2); masked-tile skip.
// ============================================================================
__global__ void __launch_bounds__(256, 2) gemm_xz(
    const __nv_bfloat16* __restrict__ Ahi, const __nv_bfloat16* __restrict__ Alo,
    int lda,
    const __nv_bfloat16* __restrict__ WhiF, const __nv_bfloat16* __restrict__ WloF,
    const __nv_bfloat16* __restrict__ WhiB, const __nv_bfloat16* __restrict__ WloB,
    const float* __restrict__ biasF, const float* __restrict__ biasB,
    float* __restrict__ Cf, float* __restrict__ Cb,
    int K, int Tcur, const unsigned char* __restrict__ mask) {
    __shared__ __align__(16) __nv_bfloat16 a_hi[128 * 24], a_lo[128 * 24];
    __shared__ __align__(16) __nv_bfloat16 w_hi[16 * 136], w_lo[16 * 136];

    const int dir = blockIdx.z;
    const int rev = dir;
    const __nv_bfloat16* Whi = dir ? WhiB : WhiF;
    const __nv_bfloat16* Wlo = dir ? WloB : WloF;
    const float* bias = dir ? biasB : biasF;
    float* C = dir ? Cb : Cf;

    const int tid  = threadIdx.x;
    const int lane = tid & 31, wid = tid >> 5;
    const int g = lane >> 2, t4 = lane & 3;
    const int warpM = wid & 3, warpN = wid >> 2;
    const int m0 = blockIdx.y << 7, n0 = blockIdx.x << 7;

    {
        const int b  = m0 / Tcur;
        const int t0 = m0 - b * Tcur;
        const int ttmin = rev ? (Tcur - 128 - t0) : t0;
        if (mask[b * Tcur + ttmin] == 0) return;
    }

    const int ar = tid >> 1;           // A row 0..127
    const int ak = (tid & 1) << 3;     // k offset 0/8
    const int wk = tid >> 4;           // W k row 0..15
    const int wc = (tid & 15) << 3;    // W col 0..120

    const __nv_bfloat16 *pAh, *pAl;
    {
        int m  = m0 + ar;
        int bi = m / Tcur;
        int t  = m - bi * Tcur;
        int tt = rev ? (Tcur - 1 - t) : t;
        size_t base = ((size_t)bi * Tcur + tt) * lda + ak;
        pAh = Ahi + base; pAl = Alo + base;
    }
    const __nv_bfloat16* pWh = Whi + (size_t)wk * 1536 + n0 + wc;
    const __nv_bfloat16* pWl = Wlo + (size_t)wk * 1536 + n0 + wc;

    const int aRowL = warpM * 32 + (lane & 15);
    const int aKofL = (lane & 16) >> 1;
    const unsigned int aHiAddr = smaddr(a_hi) + (unsigned)((aRowL * 24 + aKofL) * 2);
    const unsigned int aLoAddr = smaddr(a_lo) + (unsigned)((aRowL * 24 + aKofL) * 2);
    const int bCol = warpN * 64 + ((lane & 16) >> 1);
    const unsigned int bHiAddr = smaddr(w_hi) + (unsigned)(((lane & 15) * 136 + bCol) * 2);
    const unsigned int bLoAddr = smaddr(w_lo) + (unsigned)(((lane & 15) * 136 + bCol) * 2);

    float c_[2][8][4];
    #pragma unroll
    for (int mt = 0; mt < 2; ++mt)
        #pragma unroll
        for (int nt = 0; nt < 8; ++nt)
            #pragma unroll
            for (int i = 0; i < 4; ++i) c_[mt][nt][i] = 0.f;

    const int NT = K >> 4;
    uint4 rAh = *(const uint4*)pAh;
    uint4 rAl = *(const uint4*)pAl;
    uint4 rWh = *(const uint4*)pWh;
    uint4 rWl = *(const uint4*)pWl;

    for (int kt = 0; kt < NT; ++kt) {
        *(uint4*)(a_hi + ar * 24 + ak) = rAh;
        *(uint4*)(a_lo + ar * 24 + ak) = rAl;
        *(uint4*)(w_hi + wk * 136 + wc) = rWh;
        *(uint4*)(w_lo + wk * 136 + wc) = rWl;
        __syncthreads();

        if (kt + 1 < NT) {
            int k0 = (kt + 1) << 4;
            rAh = *(const uint4*)(pAh + k0);
            rAl = *(const uint4*)(pAl + k0);
            rWh = *(const uint4*)(pWh + (size_t)k0 * 1536);
            rWl = *(const uint4*)(pWl + (size_t)k0 * 1536);
        }

        unsigned int afh[2][4], afl[2][4];
        #pragma unroll
        for (int mt = 0; mt < 2; ++mt) {
            LDSM4(afh[mt], aHiAddr + mt * 768);
            LDSM4(afl[mt], aLoAddr + mt * 768);
        }

        #pragma unroll
        for (int p = 0; p < 4; ++p) {
            unsigned int bh[4], bl[4];
            LDSM4T(bh, bHiAddr + p * 32);
            LDSM4T(bl, bLoAddr + p * 32);
            #pragma unroll
            for (int s = 0; s < 2; ++s) {
                const int nt = 2 * p + s;
                #pragma unroll
                for (int mt = 0; mt < 2; ++mt) {
                    MMA_BF16(c_[mt][nt], afh[mt], bh[2 * s], bh[2 * s + 1]);
                    MMA_BF16(c_[mt][nt], afh[mt], bl[2 * s], bl[2 * s + 1]);
                    MMA_BF16(c_[mt][nt], afl[mt], bh[2 * s], bh[2 * s + 1]);
                }
            }
        }
        __syncthreads();
    }

    #pragma unroll
    for (int nt = 0; nt < 8; ++nt) {
        int col = n0 + warpN * 64 + nt * 8 + t4 * 2;
        float bx = __ldg(bias + col);
        float by = __ldg(bias + col + 1);
        #pragma unroll
        for (int mt = 0; mt < 2; ++mt) {
            int r = m0 + warpM * 32 + mt * 16 + g;
            float2 o0 = {c_[mt][nt][0] + bx, c_[mt][nt][1] + by};
            float2 o1 = {c_[mt][nt][2] + bx, c_[mt][nt][3] + by};
            *(float2*)(C + (size_t)r * 1536 + col)       = o0;
            *(float2*)(C + (size_t)(r + 8) * 1536 + col) = o1;
        }
    }
}

// ============================================================================
// Recurrence on tensor cores — EXACT round-6 version (proven 12.04ms config).
// SMEM: ahi[32][520] bf16 | alo[32][520] bf16 | gate[3][32][8] f32 | hp[32][8]
// ============================================================================
#define LDK 520
#define REC_SMEM (2 * 32 * LDK * 2 + 3 * 32 * 8 * 4 + 32 * 8 * 4)

__global__ void __launch_bounds__(REC_THREADS, 1) gru_rec_kernel(
    const float* __restrict__ xzf, const float* __restrict__ xzb,
    const float* __restrict__ rkf, const float* __restrict__ rkb,
    const float* __restrict__ bf,  const float* __restrict__ bb,
    const unsigned char* __restrict__ mask,
    float* __restrict__ y32,
    __nv_bfloat16* __restrict__ yhi, __nv_bfloat16* __restrict__ ylo,
    unsigned char* __restrict__ nextmask,
    int T, int flagBase, int writeHidden, float* __restrict__ hiddenOut) {
    extern __shared__ __align__(16) char smraw[];
    __nv_bfloat16* sh_ahi = (__nv_bfloat16*)smraw;                // [32][520]
    __nv_bfloat16* sh_alo = sh_ahi + 32 * LDK;                    // [32][520]
    float* sh_gate = (float*)(sh_alo + 32 * LDK);                 // [3][32][8]
    float* sh_hp   = sh_gate + 3 * 32 * 8;                        // [32][8]

    const int tid  = threadIdx.x;
    const int lane = tid & 31, wid = tid >> 5;
    const int dir = blockIdx.x >> 6;
    const int j   = blockIdx.x & 63;
    const int cb  = j << 3;
    const int b   = tid >> 3;
    const int c8  = tid & 7;
    const int col = cb + c8;

    const float* xz = dir ? xzb : xzf;
    const float* rk = dir ? rkb : rkf;
    const float* bi = (dir ? bb : bf) + 1536;   // b[1]

    for (int i = tid; i < 3 * 256 + 256; i += REC_THREADS) sh_gate[i] = 0.f;

    // ---- B-fragment preload (warps 0..5) ----
    const int gate = wid >> 1;      // 0..2
    const int mt   = wid & 1;       // 0..1
    const int t4   = lane & 3;
    const int gcol = lane >> 2;     // 0..7
    unsigned int Bh0[32], Bh1[32], Bl0[32], Bl1[32];
    if (wid < 6) {
        const float* wcolp = rk + gate * 512 + cb + gcol;
        #pragma unroll 1
        for (int kt = 0; kt < 32; ++kt) {
            int k0 = kt * 16 + t4 * 2;
            float w00 = __ldg(wcolp + (size_t)(k0)     * 1536);
            float w01 = __ldg(wcolp + (size_t)(k0 + 1) * 1536);
            float w10 = __ldg(wcolp + (size_t)(k0 + 8) * 1536);
            float w11 = __ldg(wcolp + (size_t)(k0 + 9) * 1536);
            __nv_bfloat16 h00 = __float2bfloat16(w00), h01 = __float2bfloat16(w01);
            __nv_bfloat16 h10 = __float2bfloat16(w10), h11 = __float2bfloat16(w11);
            Bh0[kt] = ((unsigned)*(unsigned short*)&h01 << 16) | *(unsigned short*)&h00;
            Bh1[kt] = ((unsigned)*(unsigned short*)&h11 << 16) | *(unsigned short*)&h10;
            Bl0[kt] = bfpack(w00 - __bfloat162float(h00), w01 - __bfloat162float(h01));
            Bl1[kt] = bfpack(w10 - __bfloat162float(h10), w11 - __bfloat162float(h11));
        }
    }
    const float bz = __ldg(bi + col);
    const float br = __ldg(bi + 512 + col);
    const float bh = __ldg(bi + 1024 + col);
    __syncthreads();

    const unsigned int aBase = smaddr(sh_ahi) +
        (unsigned)(((mt * 16 + (lane & 15)) * LDK + ((lane >> 4) << 3)) * 2);
    const unsigned int aLoBase = aBase + 32 * LDK * 2;

    unsigned int* myflag = g_flag + dir * 512 + j * 8;
    const unsigned int* pollflag = g_flag + dir * 512 + (tid & 63) * 8;
    const bool maskWriter = (nextmask != nullptr) && (dir == 0) && (j == 0) && (c8 == 0);
    unsigned char mprev = 0;

    for (int t = 0; t < T; ++t) {
        const int tsrc = dir ? (T - 1 - t) : t;
        const size_t xoff = ((size_t)b * T + t) * 1536;
        const float x0 = __ldg(xz + xoff + col);
        const float x1 = __ldg(xz + xoff + 512 + col);
        const float x2 = __ldg(xz + xoff + 1024 + col);
        const unsigned char m = mask[b * T + tsrc];

        if (t > 0) {
            if (tid < 64) {
                unsigned int v;
                unsigned int target = (unsigned int)(flagBase + t);
                do {
                    asm volatile("ld.acquire.gpu.global.u32 %0, [%1];"
                                 : "=r"(v) : "l"(pollflag) : "memory");
                } while (v < target);
            }
            __syncthreads();

            const size_t hsrc = (size_t)(((t & 1) * 2 + dir)) << 14;
            const __nv_bfloat16* ghi = g_hhi + hsrc;
            const __nv_bfloat16* glo = g_hlo + hsrc;
            #pragma unroll
            for (int q = 0; q < 8; ++q) {
                int v = q * 256 + tid;
                int bb2 = v >> 6, kc = v & 63;
                uint4 hv = __ldcg((const uint4*)(ghi + (bb2 << 9) + kc * 8));
                uint4 lv = __ldcg((const uint4*)(glo + (bb2 << 9) + kc * 8));
                *(uint4*)(sh_ahi + bb2 * LDK + kc * 8) = hv;
                *(uint4*)(sh_alo + bb2 * LDK + kc * 8) = lv;
            }
            __syncthreads();

            if (wid < 6) {
                float acc[4][4];
                #pragma unroll
                for (int i = 0; i < 4; ++i)
                    #pragma unroll
                    for (int q = 0; q < 4; ++q) acc[i][q] = 0.f;
                #pragma unroll
                for (int kt = 0; kt < 32; ++kt) {
                    unsigned int ah[4], al[4];
                    LDSM4(ah, aBase + kt * 32);
                    LDSM4(al, aLoBase + kt * 32);
                    float* c = acc[kt & 3];
                    MMA_BF16(c, ah, Bh0[kt], Bh1[kt]);
                    MMA_BF16(c, ah, Bl0[kt], Bl1[kt]);
                    MMA_BF16(c, al, Bh0[kt], Bh1[kt]);
                }
                float c0 = acc[0][0] + acc[1][0] + acc[2][0] + acc[3][0];
                float c1 = acc[0][1] + acc[1][1] + acc[2][1] + acc[3][1];
                float c2 = acc[0][2] + acc[1][2] + acc[2][2] + acc[3][2];
                float c3 = acc[0][3] + acc[1][3] + acc[2][3] + acc[3][3];
                const int row = lane >> 2, cq = (lane & 3) << 1;
                float* gp = sh_gate + gate * 256 + (mt * 16 + row) * 8 + cq;
                gp[0] = c0; gp[1] = c1;
                gp[64] = c2; gp[65] = c3;
            }
            __syncthreads();
        }

        const float iz = sh_gate[0 * 256 + b * 8 + c8] + bz;
        const float ir = sh_gate[1 * 256 + b * 8 + c8] + br;
        const float ic = sh_gate[2 * 256 + b * 8 + c8] + bh;

        const float zg = 1.f / (1.f + expf(-(x0 + iz)));
        const float rg = 1.f / (1.f + expf(-(x1 + ir)));
        const float hh = tanhf(x2 + rg * ic);
        const float hp = sh_hp[b * 8 + c8];
        const float hn = zg * hp + (1.f - zg) * hh;
        const float hsel = m ? hn : hp;
        const float yval = m ? hn : 0.f;
        sh_hp[b * 8 + c8] = hsel;

        const size_t hdst = (size_t)((((t + 1) & 1) * 2 + dir)) << 14;
        __nv_bfloat16 h16 = __float2bfloat16(hsel);
        __nv_bfloat16 l16 = __float2bfloat16(hsel - __bfloat162float(h16));
        g_hhi[hdst + (b << 9) + col] = h16;
        g_hlo[hdst + (b << 9) + col] = l16;
        __syncthreads();
        if (tid == 0) {
            unsigned int v = (unsigned int)(flagBase + t + 1);
            asm volatile("st.release.gpu.global.u32 [%0], %1;"
                         :: "l"(myflag), "r"(v) : "memory");
        }

        const size_t yidx = ((size_t)b * T + tsrc) * 1024 + (dir << 9) + col;
        if (yhi) {
            __nv_bfloat16 yh16 = __float2bfloat16(yval);
            yhi[yidx] = yh16;
            ylo[yidx] = __float2bfloat16(yval - __bfloat162float(yh16));
        }
        if (y32) y32[yidx] = yval;
        if (writeHidden && t == T - 1)
            hiddenOut[(b << 10) + (dir << 9) + col] = hsel;
        if (maskWriter) {
            if ((t & 1) == 0) mprev = m;
            else nextmask[b * (T >> 1) + (t >> 1)] = (unsigned char)(mprev | m);
        }
    }
}

// ============================================================================
// Launch sequence (graph-capturable)
// ============================================================================
extern "C" void kernel_launch(void* const* d_in, const int* in_sizes, int n_in,
                              void* d_out, int out_size) {
    (void)in_sizes; (void)n_in; (void)out_size;
    const float* inputs = (const float*)d_in[0];

    const float *k_[4][2], *r_[4][2], *bi_[4][2];
    for (int l = 0; l < 4; ++l)
        for (int d = 0; d < 2; ++d) {
            int base = 3 + l * 6 + d * 3;
            k_[l][d]  = (const float*)d_in[base + 0];
            r_[l][d]  = (const float*)d_in[base + 1];
            bi_[l][d] = (const float*)d_in[base + 2];
        }

    float *xzf, *xzb;
    unsigned char* mk;
    __nv_bfloat16 *whi, *wlo, *inhi, *inlo, *yh0, *yl0, *yh1, *yl1;
    cudaGetSymbolAddress((void**)&xzf, g_xzf);
    cudaGetSymbolAddress((void**)&xzb, g_xzb);
    cudaGetSymbolAddress((void**)&mk, g_mask);
    cudaGetSymbolAddress((void**)&whi, g_whi);
    cudaGetSymbolAddress((void**)&wlo, g_wlo);
    cudaGetSymbolAddress((void**)&inhi, g_inhi);
    cudaGetSymbolAddress((void**)&inlo, g_inlo);
    cudaGetSymbolAddress((void**)&yh0, g_yh0);
    cudaGetSymbolAddress((void**)&yl0, g_yl0);
    cudaGetSymbolAddress((void**)&yh1, g_yh1);
    cudaGetSymbolAddress((void**)&yl1, g_yl1);

    cudaFuncSetAttribute(gru_rec_kernel,
                         cudaFuncAttributeMaxDynamicSharedMemorySize, REC_SMEM);

    float* outp = (float*)d_out;
    float* hid  = outp + (size_t)32 * 128 * 1024;

    prep_kernel<<<2048, 256>>>(inputs, k_[0][0], k_[0][1], k_[1][0], k_[1][1],
                               k_[2][0], k_[2][1], k_[3][0], k_[3][1]);

    const int Ts[4]   = {1024, 512, 256, 128};
    const int Ks[4]   = {240, 2048, 2048, 2048};
    const int ldas[4] = {240, 2048, 2048, 2048};
    const int woff[4][2] = {{0, WSZ0},
                            {2 * WSZ0, 2 * WSZ0 + WSZ1},
                            {2 * WSZ0 + 2 * WSZ1, 2 * WSZ0 + 3 * WSZ1},
                            {2 * WSZ0 + 4 * WSZ1, 2 * WSZ0 + 5 * WSZ1}};
    const int moff[4]  = {0, 32768, 49152, 57344};
    const int fbase[4] = {0, 1024, 1536, 1792};

    const __nv_bfloat16* Ah[4] = {inhi, yh0, yh1, yh0};
    const __nv_bfloat16* Al[4] = {inlo, yl0, yl1, yl0};
    __nv_bfloat16* Yh[4] = {yh0, yh1, yh0, nullptr};
    __nv_bfloat16* Yl[4] = {yl0, yl1, yl0, nullptr};
    float* Y32[4] = {nullptr, nullptr, nullptr, outp};

    for (int l = 0; l < 4; ++l) {
        const int T = Ts[l], K = Ks[l];
        const int rows = 32 * T;

        dim3 grid(12, rows / 128, 2);
        gemm_xz<<<grid, 256>>>(Ah[l], Al[l], ldas[l],
                               whi + woff[l][0], wlo + woff[l][0],
                               whi + woff[l][1], wlo + woff[l][1],
                               bi_[l][0], bi_[l][1],
                               xzf, xzb, K, T, mk + moff[l]);

        gru_rec_kernel<<<128, REC_THREADS, REC_SMEM>>>(
            xzf, xzb, r_[l][0], r_[l][1], bi_[l][0], bi_[l][1],
            mk + moff[l], Y32[l], Yh[l], Yl[l],
            (l < 3) ? (mk + moff[l + 1]) : nullptr,
            T, fbase[l], (l == 3) ? 1 : 0, hid);
    }
}

// round 11
// speedup vs baseline: 1.3087x; 1.0742x over previous
#include <cuda_runtime.h>
#include <cuda_bf16.h>
#include <cstdint>

// ============================================================================
// 4-layer pyramidal BiGRU. B=32, H=512, 3H=1536.
// Layers l=0..3: T = 1024,512,256,128 ; din = 240,2048,2048,2048
// ============================================================================

#define REC_THREADS 256

// ---------------- static device scratch ----------------
__device__ float g_xzf[50331648];                 // [32][1024][1536] max
__device__ float g_xzb[50331648];
__device__ unsigned int g_flag[2 * 512];          // [dir][64 ctas] stride-8
__device__ unsigned char g_mask[65536];           // per-layer offsets
__device__ __nv_bfloat16 g_whi[19611648], g_wlo[19611648];
__device__ __nv_bfloat16 g_inhi[7864320],  g_inlo[7864320];
__device__ __nv_bfloat16 g_yh0[33554432],  g_yl0[33554432];
__device__ __nv_bfloat16 g_yh1[16777216],  g_yl1[16777216];
__device__ __nv_bfloat16 g_hhi[4 * 16384], g_hlo[4 * 16384];

// ---------------- mma / ldmatrix ----------------
#define MMA_BF16(c, a, b0, b1)                                              \
    asm volatile("mma.sync.aligned.m16n8k16.row.col.f32.bf16.bf16.f32 "     \
        "{%0,%1,%2,%3}, {%4,%5,%6,%7}, {%8,%9}, {%0,%1,%2,%3};"             \
        : "+f"((c)[0]), "+f"((c)[1]), "+f"((c)[2]), "+f"((c)[3])            \
        : "r"((a)[0]), "r"((a)[1]), "r"((a)[2]), "r"((a)[3]),               \
          "r"(b0), "r"(b1))

#define LDSM4(R, addr)                                                      \
    asm volatile("ldmatrix.sync.aligned.m8n8.x4.shared.b16 "                \
        "{%0,%1,%2,%3}, [%4];"                                              \
        : "=r"((R)[0]), "=r"((R)[1]), "=r"((R)[2]), "=r"((R)[3])            \
        : "r"(addr))

#define LDSM4T(R, addr)                                                     \
    asm volatile("ldmatrix.sync.aligned.m8n8.x4.trans.shared.b16 "          \
        "{%0,%1,%2,%3}, [%4];"                                              \
        : "=r"((R)[0]), "=r"((R)[1]), "=r"((R)[2]), "=r"((R)[3])            \
        : "r"(addr))

__device__ __forceinline__ unsigned int smaddr(const void* p) {
    return (unsigned int)__cvta_generic_to_shared(p);
}
__device__ __forceinline__ unsigned int bfpack(float a, float b) {
    __nv_bfloat162 h = __floats2bfloat162_rn(a, b);
    return *reinterpret_cast<unsigned int*>(&h);
}

// ============================================================================
// prep kernel: convert 8 weight matrices + layer-0 input to bf16 hi/lo,
// compute layer-0 mask, zero flags.
// ============================================================================
__device__ __forceinline__ void cvt4(float4 v, uint2& hi, uint2& lo) {
    __nv_bfloat162 h0 = __floats2bfloat162_rn(v.x, v.y);
    __nv_bfloat162 h1 = __floats2bfloat162_rn(v.z, v.w);
    float2 f0 = __bfloat1622float2(h0);
    float2 f1 = __bfloat1622float2(h1);
    __nv_bfloat162 l0 = __floats2bfloat162_rn(v.x - f0.x, v.y - f0.y);
    __nv_bfloat162 l1 = __floats2bfloat162_rn(v.z - f1.x, v.w - f1.y);
    hi.x = *(unsigned int*)&h0; hi.y = *(unsigned int*)&h1;
    lo.x = *(unsigned int*)&l0; lo.y = *(unsigned int*)&l1;
}

#define WSZ0 368640
#define WSZ1 3145728

__global__ void prep_kernel(const float* __restrict__ in,
                            const float* w0, const float* w1, const float* w2,
                            const float* w3, const float* w4, const float* w5,
                            const float* w6, const float* w7) {
    const float* ws[8] = {w0, w1, w2, w3, w4, w5, w6, w7};
    const int sz[8]  = {WSZ0, WSZ0, WSZ1, WSZ1, WSZ1, WSZ1, WSZ1, WSZ1};
    const int off[8] = {0, WSZ0, 2 * WSZ0, 2 * WSZ0 + WSZ1, 2 * WSZ0 + 2 * WSZ1,
                        2 * WSZ0 + 3 * WSZ1, 2 * WSZ0 + 4 * WSZ1, 2 * WSZ0 + 5 * WSZ1};
    const int gid = blockIdx.x * blockDim.x + threadIdx.x;
    const int stride = gridDim.x * blockDim.x;

    #pragma unroll 1
    for (int w = 0; w < 8; ++w) {
        const float4* W = (const float4*)ws[w];
        uint2* hi = (uint2*)(g_whi + off[w]);
        uint2* lo = (uint2*)(g_wlo + off[w]);
        int n4 = sz[w] >> 2;
        for (int i = gid; i < n4; i += stride) {
            uint2 h, l; cvt4(__ldg(W + i), h, l);
            hi[i] = h; lo[i] = l;
        }
    }
    {
        const float4* X = (const float4*)in;
        uint2* hi = (uint2*)g_inhi; uint2* lo = (uint2*)g_inlo;
        for (int i = gid; i < (7864320 >> 2); i += stride) {
            uint2 h, l; cvt4(__ldg(X + i), h, l);
            hi[i] = h; lo[i] = l;
        }
    }
    for (int r = gid; r < 32768; r += stride) {
        const float4* p = (const float4*)(in + (size_t)r * 240);
        bool any = false;
        for (int i = 0; i < 60; ++i) {
            float4 v = __ldg(p + i);
            any = any | (v.x != 0.f) | (v.y != 0.f) | (v.z != 0.f) | (v.w != 0.f);
            if (any) break;
        }
        g_mask[r] = any ? 1 : 0;
    }
    for (int i = gid; i < 2 * 512; i += stride) g_flag[i] = 0u;
}

// ============================================================================
// Input-projection GEMM — EXACT round-10 version (proven best):
// bf16 hi/lo, mma.sync, tile 128x128x16, 2 CTAs/SM, masked-tile skip.
// ============================================================================
__global__ void __launch_bounds__(256, 2) gemm_xz(
    const __nv_bfloat16* __restrict__ Ahi, const __nv_bfloat16* __restrict__ Alo,
    int lda,
    const __nv_bfloat16* __restrict__ WhiF, const __nv_bfloat16* __restrict__ WloF,
    const __nv_bfloat16* __restrict__ WhiB, const __nv_bfloat16* __restrict__ WloB,
    const float* __restrict__ biasF, const float* __restrict__ biasB,
    float* __restrict__ Cf, float* __restrict__ Cb,
    int K, int Tcur, const unsigned char* __restrict__ mask) {
    __shared__ __align__(16) __nv_bfloat16 a_hi[128 * 24], a_lo[128 * 24];
    __shared__ __align__(16) __nv_bfloat16 w_hi[16 * 136], w_lo[16 * 136];

    const int dir = blockIdx.z;
    const int rev = dir;
    const __nv_bfloat16* Whi = dir ? WhiB : WhiF;
    const __nv_bfloat16* Wlo = dir ? WloB : WloF;
    const float* bias = dir ? biasB : biasF;
    float* C = dir ? Cb : Cf;

    const int tid  = threadIdx.x;
    const int lane = tid & 31, wid = tid >> 5;
    const int g = lane >> 2, t4 = lane & 3;
    const int warpM = wid & 3, warpN = wid >> 2;
    const int m0 = blockIdx.y << 7, n0 = blockIdx.x << 7;

    {
        const int b  = m0 / Tcur;
        const int t0 = m0 - b * Tcur;
        const int ttmin = rev ? (Tcur - 128 - t0) : t0;
        if (mask[b * Tcur + ttmin] == 0) return;
    }

    const int ar = tid >> 1;
    const int ak = (tid & 1) << 3;
    const int wk = tid >> 4;
    const int wc = (tid & 15) << 3;

    const __nv_bfloat16 *pAh, *pAl;
    {
        int m  = m0 + ar;
        int bi = m / Tcur;
        int t  = m - bi * Tcur;
        int tt = rev ? (Tcur - 1 - t) : t;
        size_t base = ((size_t)bi * Tcur + tt) * lda + ak;
        pAh = Ahi + base; pAl = Alo + base;
    }
    const __nv_bfloat16* pWh = Whi + (size_t)wk * 1536 + n0 + wc;
    const __nv_bfloat16* pWl = Wlo + (size_t)wk * 1536 + n0 + wc;

    const int aRowL = warpM * 32 + (lane & 15);
    const int aKofL = (lane & 16) >> 1;
    const unsigned int aHiAddr = smaddr(a_hi) + (unsigned)((aRowL * 24 + aKofL) * 2);
    const unsigned int aLoAddr = smaddr(a_lo) + (unsigned)((aRowL * 24 + aKofL) * 2);
    const int bCol = warpN * 64 + ((lane & 16) >> 1);
    const unsigned int bHiAddr = smaddr(w_hi) + (unsigned)(((lane & 15) * 136 + bCol) * 2);
    const unsigned int bLoAddr = smaddr(w_lo) + (unsigned)(((lane & 15) * 136 + bCol) * 2);

    float c_[2][8][4];
    #pragma unroll
    for (int mt = 0; mt < 2; ++mt)
        #pragma unroll
        for (int nt = 0; nt < 8; ++nt)
            #pragma unroll
            for (int i = 0; i < 4; ++i) c_[mt][nt][i] = 0.f;

    const int NT = K >> 4;
    uint4 rAh = *(const uint4*)pAh;
    uint4 rAl = *(const uint4*)pAl;
    uint4 rWh = *(const uint4*)pWh;
    uint4 rWl = *(const uint4*)pWl;

    for (int kt = 0; kt < NT; ++kt) {
        *(uint4*)(a_hi + ar * 24 + ak) = rAh;
        *(uint4*)(a_lo + ar * 24 + ak) = rAl;
        *(uint4*)(w_hi + wk * 136 + wc) = rWh;
        *(uint4*)(w_lo + wk * 136 + wc) = rWl;
        __syncthreads();

        if (kt + 1 < NT) {
            int k0 = (kt + 1) << 4;
            rAh = *(const uint4*)(pAh + k0);
            rAl = *(const uint4*)(pAl + k0);
            rWh = *(const uint4*)(pWh + (size_t)k0 * 1536);
            rWl = *(const uint4*)(pWl + (size_t)k0 * 1536);
        }

        unsigned int afh[2][4], afl[2][4];
        #pragma unroll
        for (int mt = 0; mt < 2; ++mt) {
            LDSM4(afh[mt], aHiAddr + mt * 768);
            LDSM4(afl[mt], aLoAddr + mt * 768);
        }

        #pragma unroll
        for (int p = 0; p < 4; ++p) {
            unsigned int bh[4], bl[4];
            LDSM4T(bh, bHiAddr + p * 32);
            LDSM4T(bl, bLoAddr + p * 32);
            #pragma unroll
            for (int s = 0; s < 2; ++s) {
                const int nt = 2 * p + s;
                #pragma unroll
                for (int mt = 0; mt < 2; ++mt) {
                    MMA_BF16(c_[mt][nt], afh[mt], bh[2 * s], bh[2 * s + 1]);
                    MMA_BF16(c_[mt][nt], afh[mt], bl[2 * s], bl[2 * s + 1]);
                    MMA_BF16(c_[mt][nt], afl[mt], bh[2 * s], bh[2 * s + 1]);
                }
            }
        }
        __syncthreads();
    }

    #pragma unroll
    for (int nt = 0; nt < 8; ++nt) {
        int col = n0 + warpN * 64 + nt * 8 + t4 * 2;
        float bx = __ldg(bias + col);
        float by = __ldg(bias + col + 1);
        #pragma unroll
        for (int mt = 0; mt < 2; ++mt) {
            int r = m0 + warpM * 32 + mt * 16 + g;
            float2 o0 = {c_[mt][nt][0] + bx, c_[mt][nt][1] + by};
            float2 o1 = {c_[mt][nt][2] + bx, c_[mt][nt][3] + by};
            *(float2*)(C + (size_t)r * 1536 + col)       = o0;
            *(float2*)(C + (size_t)(r + 8) * 1536 + col) = o1;
        }
    }
}

// ============================================================================
// Recurrence on tensor cores, K-SPLIT across 8 warps (crossbar fix):
//   Warp w owns kt in [4w, 4w+4): computes ALL 3 gates x 2 mt for its chunk.
//   LDSM/step: 128 x4 (vs 384 in round-6); mma balanced 144/SMSP.
//   Staging: round-6 proven __ldcg register-prefetch loop (NOT cp.async).
//   Partials [8][3][256] reduced in the scalar epilogue (guarded by t>0).
// SMEM: ahi[32][520] | alo[32][520] bf16 | part[8][3][256] f32 | hp[256]
// ============================================================================
#define LDK 520
#define REC_SMEM (2 * 32 * LDK * 2 + 8 * 3 * 256 * 4 + 256 * 4)

__global__ void __launch_bounds__(REC_THREADS, 1) gru_rec_kernel(
    const float* __restrict__ xzf, const float* __restrict__ xzb,
    const float* __restrict__ rkf, const float* __restrict__ rkb,
    const float* __restrict__ bf,  const float* __restrict__ bb,
    const unsigned char* __restrict__ mask,
    float* __restrict__ y32,
    __nv_bfloat16* __restrict__ yhi, __nv_bfloat16* __restrict__ ylo,
    unsigned char* __restrict__ nextmask,
    int T, int flagBase, int writeHidden, float* __restrict__ hiddenOut) {
    extern __shared__ __align__(16) char smraw[];
    __nv_bfloat16* sh_ahi = (__nv_bfloat16*)smraw;                // [32][520]
    __nv_bfloat16* sh_alo = sh_ahi + 32 * LDK;                    // [32][520]
    float* sh_part = (float*)(sh_alo + 32 * LDK);                 // [8][3][256]
    float* sh_hp   = sh_part + 8 * 3 * 256;                       // [256]

    const int tid  = threadIdx.x;
    const int lane = tid & 31, wid = tid >> 5;
    const int dir = blockIdx.x >> 6;
    const int j   = blockIdx.x & 63;
    const int cb  = j << 3;
    const int b   = tid >> 3;
    const int c8  = tid & 7;
    const int col = cb + c8;

    const float* xz = dir ? xzb : xzf;
    const float* rk = dir ? rkb : rkf;
    const float* bi = (dir ? bb : bf) + 1536;   // b[1]

    sh_hp[tid] = 0.f;

    // ---- B-fragment preload: warp w owns kt = 4w..4w+3, all 3 gates ----
    const int t4 = lane & 3;
    const int gcol = lane >> 2;
    unsigned int Bh0[3][4], Bh1[3][4], Bl0[3][4], Bl1[3][4];
    #pragma unroll 1
    for (int gate = 0; gate < 3; ++gate) {
        const float* wcolp = rk + gate * 512 + cb + gcol;
        #pragma unroll
        for (int q = 0; q < 4; ++q) {
            int k0 = (wid * 4 + q) * 16 + t4 * 2;
            float w00 = __ldg(wcolp + (size_t)(k0)     * 1536);
            float w01 = __ldg(wcolp + (size_t)(k0 + 1) * 1536);
            float w10 = __ldg(wcolp + (size_t)(k0 + 8) * 1536);
            float w11 = __ldg(wcolp + (size_t)(k0 + 9) * 1536);
            __nv_bfloat16 h00 = __float2bfloat16(w00), h01 = __float2bfloat16(w01);
            __nv_bfloat16 h10 = __float2bfloat16(w10), h11 = __float2bfloat16(w11);
            Bh0[gate][q] = ((unsigned)*(unsigned short*)&h01 << 16) | *(unsigned short*)&h00;
            Bh1[gate][q] = ((unsigned)*(unsigned short*)&h11 << 16) | *(unsigned short*)&h10;
            Bl0[gate][q] = bfpack(w00 - __bfloat162float(h00), w01 - __bfloat162float(h01));
            Bl1[gate][q] = bfpack(w10 - __bfloat162float(h10), w11 - __bfloat162float(h11));
        }
    }
    const float bz = __ldg(bi + col);
    const float br = __ldg(bi + 512 + col);
    const float bh = __ldg(bi + 1024 + col);
    __syncthreads();

    // ldmatrix bases: rows (lane&15) for mt0 / +16 for mt1, k-chunk = wid*4 kt
    const unsigned int aB0 = smaddr(sh_ahi) +
        (unsigned)((((lane & 15)) * LDK + ((lane >> 4) << 3)) * 2) + (unsigned)(wid * 128);
    const unsigned int aB1 = aB0 + (unsigned)(16 * LDK * 2);
    const unsigned int loOfs = (unsigned)(32 * LDK * 2);

    unsigned int* myflag = g_flag + dir * 512 + j * 8;
    const unsigned int* pollflag = g_flag + dir * 512 + (tid & 63) * 8;
    const bool maskWriter = (nextmask != nullptr) && (dir == 0) && (j == 0) && (c8 == 0);
    unsigned char mprev = 0;

    for (int t = 0; t < T; ++t) {
        const int tsrc = dir ? (T - 1 - t) : t;
        const size_t xoff = ((size_t)b * T + t) * 1536;
        const float x0 = __ldg(xz + xoff + col);
        const float x1 = __ldg(xz + xoff + 512 + col);
        const float x2 = __ldg(xz + xoff + 1024 + col);
        const unsigned char m = mask[b * T + tsrc];

        if (t > 0) {
            // ---- wait for step t-1 of all CTAs in this direction ----
            if (tid < 64) {
                unsigned int v;
                unsigned int target = (unsigned int)(flagBase + t);
                do {
                    asm volatile("ld.acquire.gpu.global.u32 %0, [%1];"
                                 : "=r"(v) : "l"(pollflag) : "memory");
                } while (v < target);
            }
            __syncthreads();

            // ---- stage h (bf16 hi/lo) — round-6 proven register-prefetch ----
            const size_t hsrc = (size_t)(((t & 1) * 2 + dir)) << 14;
            const __nv_bfloat16* ghi = g_hhi + hsrc;
            const __nv_bfloat16* glo = g_hlo + hsrc;
            #pragma unroll
            for (int q = 0; q < 8; ++q) {
                int v = q * 256 + tid;
                int bb2 = v >> 6, kc = v & 63;
                uint4 hv = __ldcg((const uint4*)(ghi + (bb2 << 9) + kc * 8));
                uint4 lv = __ldcg((const uint4*)(glo + (bb2 << 9) + kc * 8));
                *(uint4*)(sh_ahi + bb2 * LDK + kc * 8) = hv;
                *(uint4*)(sh_alo + bb2 * LDK + kc * 8) = lv;
            }
            __syncthreads();

            // ---- each warp: 4 kt x (4 LDSM + 18 mma), all gates/mt ----
            float acc[3][2][4];
            #pragma unroll
            for (int gg = 0; gg < 3; ++gg)
                #pragma unroll
                for (int mt = 0; mt < 2; ++mt)
                    #pragma unroll
                    for (int i = 0; i < 4; ++i) acc[gg][mt][i] = 0.f;

            #pragma unroll
            for (int q = 0; q < 4; ++q) {
                unsigned int ah[2][4], al[2][4];
                LDSM4(ah[0], aB0 + q * 32);
                LDSM4(ah[1], aB1 + q * 32);
                LDSM4(al[0], aB0 + loOfs + q * 32);
                LDSM4(al[1], aB1 + loOfs + q * 32);
                #pragma unroll
                for (int gg = 0; gg < 3; ++gg) {
                    #pragma unroll
                    for (int mt = 0; mt < 2; ++mt) {
                        MMA_BF16(acc[gg][mt], ah[mt], Bh0[gg][q], Bh1[gg][q]);
                        MMA_BF16(acc[gg][mt], ah[mt], Bl0[gg][q], Bl1[gg][q]);
                        MMA_BF16(acc[gg][mt], al[mt], Bh0[gg][q], Bh1[gg][q]);
                    }
                }
            }
            // partial store
            const int row = lane >> 2, cq = (lane & 3) << 1;
            #pragma unroll
            for (int gg = 0; gg < 3; ++gg) {
                #pragma unroll
                for (int mt = 0; mt < 2; ++mt) {
                    float* gp = sh_part + (wid * 3 + gg) * 256 + (mt * 16 + row) * 8 + cq;
                    gp[0]  = acc[gg][mt][0];
                    gp[1]  = acc[gg][mt][1];
                    gp[64] = acc[gg][mt][2];
                    gp[65] = acc[gg][mt][3];
                }
            }
            __syncthreads();
        }

        // ---- scalar epilogue: reduce 8 partials per gate ----
        float iz = bz, ir = br, ic = bh;
        if (t > 0) {
            #pragma unroll
            for (int w = 0; w < 8; ++w) {
                iz += sh_part[(w * 3 + 0) * 256 + tid];
                ir += sh_part[(w * 3 + 1) * 256 + tid];
                ic += sh_part[(w * 3 + 2) * 256 + tid];
            }
        }

        const float zg = 1.f / (1.f + expf(-(x0 + iz)));
        const float rg = 1.f / (1.f + expf(-(x1 + ir)));
        const float hh = tanhf(x2 + rg * ic);
        const float hp = sh_hp[tid];
        const float hn = zg * hp + (1.f - zg) * hh;
        const float hsel = m ? hn : hp;
        const float yval = m ? hn : 0.f;
        sh_hp[tid] = hsel;

        // ---- critical path: publish h (bf16 hi/lo) + flag ----
        const size_t hdst = (size_t)((((t + 1) & 1) * 2 + dir)) << 14;
        __nv_bfloat16 h16 = __float2bfloat16(hsel);
        __nv_bfloat16 l16 = __float2bfloat16(hsel - __bfloat162float(h16));
        g_hhi[hdst + (b << 9) + col] = h16;
        g_hlo[hdst + (b << 9) + col] = l16;
        __syncthreads();
        if (tid == 0) {
            unsigned int v = (unsigned int)(flagBase + t + 1);
            asm volatile("st.release.gpu.global.u32 [%0], %1;"
                         :: "l"(myflag), "r"(v) : "memory");
        }

        // ---- off critical path: outputs ----
        const size_t yidx = ((size_t)b * T + tsrc) * 1024 + (dir << 9) + col;
        if (yhi) {
            __nv_bfloat16 yh16 = __float2bfloat16(yval);
            yhi[yidx] = yh16;
            ylo[yidx] = __float2bfloat16(yval - __bfloat162float(yh16));
        }
        if (y32) y32[yidx] = yval;
        if (writeHidden && t == T - 1)
            hiddenOut[(b << 10) + (dir << 9) + col] = hsel;
        if (maskWriter) {
            if ((t & 1) == 0) mprev = m;
            else nextmask[b * (T >> 1) + (t >> 1)] = (unsigned char)(mprev | m);
        }
    }
}

// ============================================================================
// Launch sequence (graph-capturable)
// ============================================================================
extern "C" void kernel_launch(void* const* d_in, const int* in_sizes, int n_in,
                              void* d_out, int out_size) {
    (void)in_sizes; (void)n_in; (void)out_size;
    const float* inputs = (const float*)d_in[0];

    const float *k_[4][2], *r_[4][2], *bi_[4][2];
    for (int l = 0; l < 4; ++l)
        for (int d = 0; d < 2; ++d) {
            int base = 3 + l * 6 + d * 3;
            k_[l][d]  = (const float*)d_in[base + 0];
            r_[l][d]  = (const float*)d_in[base + 1];
            bi_[l][d] = (const float*)d_in[base + 2];
        }

    float *xzf, *xzb;
    unsigned char* mk;
    __nv_bfloat16 *whi, *wlo, *inhi, *inlo, *yh0, *yl0, *yh1, *yl1;
    cudaGetSymbolAddress((void**)&xzf, g_xzf);
    cudaGetSymbolAddress((void**)&xzb, g_xzb);
    cudaGetSymbolAddress((void**)&mk, g_mask);
    cudaGetSymbolAddress((void**)&whi, g_whi);
    cudaGetSymbolAddress((void**)&wlo, g_wlo);
    cudaGetSymbolAddress((void**)&inhi, g_inhi);
    cudaGetSymbolAddress((void**)&inlo, g_inlo);
    cudaGetSymbolAddress((void**)&yh0, g_yh0);
    cudaGetSymbolAddress((void**)&yl0, g_yl0);
    cudaGetSymbolAddress((void**)&yh1, g_yh1);
    cudaGetSymbolAddress((void**)&yl1, g_yl1);

    cudaFuncSetAttribute(gru_rec_kernel,
                         cudaFuncAttributeMaxDynamicSharedMemorySize, REC_SMEM);

    float* outp = (float*)d_out;
    float* hid  = outp + (size_t)32 * 128 * 1024;

    prep_kernel<<<2048, 256>>>(inputs, k_[0][0], k_[0][1], k_[1][0], k_[1][1],
                               k_[2][0], k_[2][1], k_[3][0], k_[3][1]);

    const int Ts[4]   = {1024, 512, 256, 128};
    const int Ks[4]   = {240, 2048, 2048, 2048};
    const int ldas[4] = {240, 2048, 2048, 2048};
    const int woff[4][2] = {{0, WSZ0},
                            {2 * WSZ0, 2 * WSZ0 + WSZ1},
                            {2 * WSZ0 + 2 * WSZ1, 2 * WSZ0 + 3 * WSZ1},
                            {2 * WSZ0 + 4 * WSZ1, 2 * WSZ0 + 5 * WSZ1}};
    const int moff[4]  = {0, 32768, 49152, 57344};
    const int fbase[4] = {0, 1024, 1536, 1792};

    const __nv_bfloat16* Ah[4] = {inhi, yh0, yh1, yh0};
    const __nv_bfloat16* Al[4] = {inlo, yl0, yl1, yl0};
    __nv_bfloat16* Yh[4] = {yh0, yh1, yh0, nullptr};
    __nv_bfloat16* Yl[4] = {yl0, yl1, yl0, nullptr};
    float* Y32[4] = {nullptr, nullptr, nullptr, outp};

    for (int l = 0; l < 4; ++l) {
        const int T = Ts[l], K = Ks[l];
        const int rows = 32 * T;

        dim3 grid(12, rows / 128, 2);
        gemm_xz<<<grid, 256>>>(Ah[l], Al[l], ldas[l],
                               whi + woff[l][0], wlo + woff[l][0],
                               whi + woff[l][1], wlo + woff[l][1],
                               bi_[l][0], bi_[l][1],
                               xzf, xzb, K, T, mk + moff[l]);

        gru_rec_kernel<<<128, REC_THREADS, REC_SMEM>>>(
            xzf, xzb, r_[l][0], r_[l][1], bi_[l][0], bi_[l][1],
            mk + moff[l], Y32[l], Yh[l], Yl[l],
            (l < 3) ? (mk + moff[l + 1]) : nullptr,
            T, fbase[l], (l == 3) ? 1 : 0, hid);
    }
}